// round 9
// baseline (speedup 1.0000x reference)
#include <cuda_runtime.h>
#include <cuda_bf16.h>
#include <math.h>
#include <stdint.h>

#define S_LEN 4096
#define H_DIM 2048
#define HQ 8
#define HKV 4
#define HD 256
#define WIN 1024

// ================= portable PTX helpers (baseline ISA only) =================
__device__ __forceinline__ uint32_t smem_u32(const void* p) {
    uint32_t a;
    asm("{ .reg .u64 t; cvta.to.shared.u64 t, %1; cvt.u32.u64 %0, t; }"
        : "=r"(a) : "l"(p));
    return a;
}

#define CP_ASYNC16(dst_u32, src_ptr) \
    asm volatile("cp.async.cg.shared.global [%0], [%1], 16;" \
                 :: "r"(dst_u32), "l"(src_ptr) : "memory")
#define CP_COMMIT() asm volatile("cp.async.commit_group;" ::: "memory")
#define CP_WAIT1()  asm volatile("cp.async.wait_group 1;" ::: "memory")

__device__ __forceinline__ void mma16816(float* d, const uint32_t* a,
                                         uint32_t b0, uint32_t b1) {
    asm volatile(
        "mma.sync.aligned.m16n8k16.row.col.f32.bf16.bf16.f32 "
        "{%0,%1,%2,%3}, {%4,%5,%6,%7}, {%8,%9}, {%0,%1,%2,%3};"
        : "+f"(d[0]), "+f"(d[1]), "+f"(d[2]), "+f"(d[3])
        : "r"(a[0]), "r"(a[1]), "r"(a[2]), "r"(a[3]), "r"(b0), "r"(b1));
}

__device__ __forceinline__ void ldsm4(uint32_t* r, uint32_t addr) {
    asm volatile("ldmatrix.sync.aligned.m8n8.x4.shared.b16 {%0,%1,%2,%3}, [%4];"
                 : "=r"(r[0]), "=r"(r[1]), "=r"(r[2]), "=r"(r[3]) : "r"(addr));
}
__device__ __forceinline__ void ldsm4t(uint32_t* r, uint32_t addr) {
    asm volatile("ldmatrix.sync.aligned.m8n8.x4.trans.shared.b16 {%0,%1,%2,%3}, [%4];"
                 : "=r"(r[0]), "=r"(r[1]), "=r"(r[2]), "=r"(r[3]) : "r"(addr));
}

__device__ __forceinline__ uint32_t pack2bf(float a, float b) {
    __nv_bfloat162 t = __floats2bfloat162_rn(a, b);
    return *(uint32_t*)&t;
}

// ================= scratch (device globals) =================
__device__ float g_Qp[S_LEN * (HQ * HD)];
__device__ float g_Kp[S_LEN * (HKV * HD)];
__device__ float g_Vp[S_LEN * (HKV * HD)];

__device__ __nv_bfloat16 g_hid_h[S_LEN * H_DIM];
__device__ __nv_bfloat16 g_hid_l[S_LEN * H_DIM];
__device__ __nv_bfloat16 g_wq_h[HQ * HD * H_DIM];
__device__ __nv_bfloat16 g_wq_l[HQ * HD * H_DIM];
__device__ __nv_bfloat16 g_wk_h[HKV * HD * H_DIM];
__device__ __nv_bfloat16 g_wk_l[HKV * HD * H_DIM];
__device__ __nv_bfloat16 g_wv_h[HKV * HD * H_DIM];
__device__ __nv_bfloat16 g_wv_l[HKV * HD * H_DIM];
__device__ __nv_bfloat16 g_wo_h[H_DIM * HQ * HD];
__device__ __nv_bfloat16 g_wo_l[H_DIM * HQ * HD];
__device__ __nv_bfloat16 g_ao_h[S_LEN * HQ * HD];
__device__ __nv_bfloat16 g_ao_l[S_LEN * HQ * HD];

__device__ __nv_bfloat16 g_qr_h[HQ * S_LEN * HD];
__device__ __nv_bfloat16 g_qr_l[HQ * S_LEN * HD];
__device__ __nv_bfloat16 g_kr_h[HKV * S_LEN * HD];
__device__ __nv_bfloat16 g_kr_l[HKV * S_LEN * HD];
__device__ __nv_bfloat16 g_vr_h[HKV * S_LEN * HD];
__device__ __nv_bfloat16 g_vr_l[HKV * S_LEN * HD];

// ================= fused fp32 -> bf16 hi/lo split (all 5 tensors) ==========
#define N4_HID (S_LEN * H_DIM / 4)
#define N4_WQ  (HQ * HD * H_DIM / 4)
#define N4_WK  (HKV * HD * H_DIM / 4)
#define N4_WV  (HKV * HD * H_DIM / 4)
#define N4_WO  (H_DIM * HQ * HD / 4)
#define N4_TOT (N4_HID + N4_WQ + N4_WK + N4_WV + N4_WO)

__global__ __launch_bounds__(256)
void cvt_all(const float4* __restrict__ hid, const float4* __restrict__ wq,
             const float4* __restrict__ wk, const float4* __restrict__ wv,
             const float4* __restrict__ wo,
             __nv_bfloat16* __restrict__ hidh, __nv_bfloat16* __restrict__ hidl,
             __nv_bfloat16* __restrict__ wqh,  __nv_bfloat16* __restrict__ wql,
             __nv_bfloat16* __restrict__ wkh,  __nv_bfloat16* __restrict__ wkl,
             __nv_bfloat16* __restrict__ wvh,  __nv_bfloat16* __restrict__ wvl,
             __nv_bfloat16* __restrict__ woh,  __nv_bfloat16* __restrict__ wol) {
    int i = blockIdx.x * blockDim.x + threadIdx.x;
    if (i >= N4_TOT) return;
    const float4* src;
    __nv_bfloat16 *hi, *lo;
    int j = i;
    if (j < N4_HID) { src = hid; hi = hidh; lo = hidl; }
    else if ((j -= N4_HID) < N4_WQ) { src = wq; hi = wqh; lo = wql; }
    else if ((j -= N4_WQ) < N4_WK)  { src = wk; hi = wkh; lo = wkl; }
    else if ((j -= N4_WK) < N4_WV)  { src = wv; hi = wvh; lo = wvl; }
    else { j -= N4_WV; src = wo; hi = woh; lo = wol; }
    float4 v = src[j];
    union { ushort4 u; __nv_bfloat16 b[4]; } H, L;
    H.b[0] = __float2bfloat16(v.x);
    H.b[1] = __float2bfloat16(v.y);
    H.b[2] = __float2bfloat16(v.z);
    H.b[3] = __float2bfloat16(v.w);
    L.b[0] = __float2bfloat16(v.x - __bfloat162float(H.b[0]));
    L.b[1] = __float2bfloat16(v.y - __bfloat162float(H.b[1]));
    L.b[2] = __float2bfloat16(v.z - __bfloat162float(H.b[2]));
    L.b[3] = __float2bfloat16(v.w - __bfloat162float(H.b[3]));
    *(ushort4*)(hi + 4 * (size_t)j) = H.u;
    *(ushort4*)(lo + 4 * (size_t)j) = L.u;
}

// ================= HMMA bf16x3 GEMM: C[M,N] = A[M,K] @ B[N,K]^T ============
// CTA 128x128, 128 threads (4 warps 2x2), warp tile 64x64, BK=32.
// 3-stage cp.async ring, XOR-swizzled smem, term-major mma emission.
#define G_MAT 8192                 // 128 rows x 64B
#define G_SS  (4 * G_MAT)          // Ah, Al, Bh, Bl
#define SMEM_GEMM (3 * G_SS)

__device__ __forceinline__ uint32_t gsw(int r, int c) {   // c = 16B chunk 0..3
    return (uint32_t)(r * 64 + ((c ^ (r & 3)) * 16));
}

__global__ __launch_bounds__(128, 2)
void gemm_bf16x3(const __nv_bfloat16* __restrict__ Ah, const __nv_bfloat16* __restrict__ Al,
                 const __nv_bfloat16* __restrict__ Bh, const __nv_bfloat16* __restrict__ Bl,
                 float* __restrict__ C, int N, int K) {
    extern __shared__ char smemc[];
    const uint32_t sb = smem_u32(smemc);
    const int tid = threadIdx.x;
    const int lane = tid & 31;
    const int w = tid >> 5;
    const int wm = (w >> 1) * 64;
    const int wn = (w & 1) * 64;
    const int bm = blockIdx.y * 128;
    const int bn = blockIdx.x * 128;
    const int nkb = K / 32;

    const __nv_bfloat16* mats[4] = {Ah, Al, Bh, Bl};
    const int rowoff[4] = {bm, bm, bn, bn};

    auto load_stage = [&](int s, int kblk) {
        const uint32_t st = sb + s * G_SS;
#pragma unroll
        for (int m = 0; m < 4; m++) {
            const __nv_bfloat16* src = mats[m] + (size_t)rowoff[m] * K + kblk;
            const uint32_t dstb = st + m * G_MAT;
#pragma unroll
            for (int i = 0; i < 4; i++) {
                int flat = tid + i * 128;
                int r = flat >> 2, c = flat & 3;
                CP_ASYNC16(dstb + gsw(r, c), src + (size_t)r * K + c * 8);
            }
        }
    };

    float acc[4][8][4];
#pragma unroll
    for (int i = 0; i < 4; i++)
#pragma unroll
        for (int j = 0; j < 8; j++)
#pragma unroll
            for (int q = 0; q < 4; q++) acc[i][j][q] = 0.f;

    load_stage(0, 0);  CP_COMMIT();
    load_stage(1, 32); CP_COMMIT();
    load_stage(2, 64); CP_COMMIT();

    const int aro = (lane & 7) + 8 * ((lane >> 3) & 1);
    const int acs = (lane >> 4);
    const int bro = (lane & 7) + 8 * ((lane >> 4) & 1);
    const int bcs = ((lane >> 3) & 1);

    int s = 0;
    for (int kb = 0; kb < nkb; kb++) {
        CP_WAIT1();
        __syncthreads();
        if (kb >= 1 && kb + 2 < nkb) load_stage((kb + 2) % 3, (kb + 2) * 32);
        if (kb >= 1) CP_COMMIT();
        const uint32_t st = sb + s * G_SS;

#pragma unroll
        for (int kk = 0; kk < 2; kk++) {
            uint32_t ah[4][4], al[4][4];
#pragma unroll
            for (int i = 0; i < 4; i++) {
                int r = wm + i * 16 + aro;
                uint32_t ab = st + gsw(r, kk * 2 + acs);
                ldsm4(ah[i], ab);
                ldsm4(al[i], ab + G_MAT);
            }
#pragma unroll
            for (int jp = 0; jp < 4; jp++) {
                uint32_t bh[4], bl[4];
                int r = wn + jp * 16 + bro;
                uint32_t bb = st + 2 * G_MAT + gsw(r, kk * 2 + bcs);
                ldsm4(bh, bb);
                ldsm4(bl, bb + G_MAT);
                // term-major emission: RAW distance 8 on each accumulator
#pragma unroll
                for (int i = 0; i < 4; i++) {
                    mma16816(acc[i][2 * jp],     ah[i], bh[0], bh[1]);
                    mma16816(acc[i][2 * jp + 1], ah[i], bh[2], bh[3]);
                }
#pragma unroll
                for (int i = 0; i < 4; i++) {
                    mma16816(acc[i][2 * jp],     ah[i], bl[0], bl[1]);
                    mma16816(acc[i][2 * jp + 1], ah[i], bl[2], bl[3]);
                }
#pragma unroll
                for (int i = 0; i < 4; i++) {
                    mma16816(acc[i][2 * jp],     al[i], bh[0], bh[1]);
                    mma16816(acc[i][2 * jp + 1], al[i], bh[2], bh[3]);
                }
            }
        }
        s = (s == 2) ? 0 : s + 1;
    }

    const int lr = lane >> 2;
    const int lc = lane & 3;
#pragma unroll
    for (int i = 0; i < 4; i++) {
        const int r0 = bm + wm + i * 16 + lr;
#pragma unroll
        for (int j = 0; j < 8; j++) {
            const int c0 = bn + wn + j * 8 + lc * 2;
            *(float2*)(C + (size_t)r0 * N + c0) = make_float2(acc[i][j][0], acc[i][j][1]);
            *(float2*)(C + (size_t)(r0 + 8) * N + c0) = make_float2(acc[i][j][2], acc[i][j][3]);
        }
    }
}

// ======= RMSNorm + RoPE -> bf16 hi/lo head-major (1 block per position) =====
__global__ __launch_bounds__(256)
void norm_rope2(const float* __restrict__ Qp, const float* __restrict__ Kp,
                const float* __restrict__ Vp,
                const float* __restrict__ cosb, const float* __restrict__ sinb,
                const float* __restrict__ qw, const float* __restrict__ kw,
                __nv_bfloat16* __restrict__ Qrh, __nv_bfloat16* __restrict__ Qrl,
                __nv_bfloat16* __restrict__ Krh, __nv_bfloat16* __restrict__ Krl,
                __nv_bfloat16* __restrict__ Vrh, __nv_bfloat16* __restrict__ Vrl) {
    const int s = blockIdx.x;
    const int d = threadIdx.x;

    __shared__ float cs[HD], sn[HD], qws[HD], kws[HD], red[8], ysh[HD];
    cs[d]  = cosb[(size_t)s * HD + d];
    sn[d]  = sinb[(size_t)s * HD + d];
    qws[d] = qw[d];
    kws[d] = kw[d];
    __syncthreads();

    for (int hh = 0; hh < HQ + 2 * HKV; hh++) {
        const float* src;
        __nv_bfloat16 *dsth, *dstl;
        const float* wv = nullptr;
        bool do_rope = false;

        if (hh < HQ) {
            src = Qp + (size_t)s * (HQ * HD) + hh * HD;
            dsth = Qrh + ((size_t)hh * S_LEN + s) * HD;
            dstl = Qrl + ((size_t)hh * S_LEN + s) * HD;
            wv = qws; do_rope = true;
        } else if (hh < HQ + HKV) {
            int h = hh - HQ;
            src = Kp + (size_t)s * (HKV * HD) + h * HD;
            dsth = Krh + ((size_t)h * S_LEN + s) * HD;
            dstl = Krl + ((size_t)h * S_LEN + s) * HD;
            wv = kws; do_rope = true;
        } else {
            int h = hh - HQ - HKV;
            src = Vp + (size_t)s * (HKV * HD) + h * HD;
            dsth = Vrh + ((size_t)h * S_LEN + s) * HD;
            dstl = Vrl + ((size_t)h * S_LEN + s) * HD;
        }

        float x = src[d];
        float v = x * x;
#pragma unroll
        for (int off = 16; off > 0; off >>= 1)
            v += __shfl_xor_sync(0xffffffffu, v, off);
        if ((d & 31) == 0) red[d >> 5] = v;
        __syncthreads();
        float tot = 0.f;
#pragma unroll
        for (int r = 0; r < 8; r++) tot += red[r];

        float rms = rsqrtf(tot * (1.0f / HD) + 1e-6f);
        float y = x * rms;
        if (wv) y *= wv[d];

        if (do_rope) {
            ysh[d] = y;
            __syncthreads();
            float rot = (d < HD / 2) ? -ysh[d + HD / 2] : ysh[d - HD / 2];
            y = y * cs[d] + rot * sn[d];
        }
        __nv_bfloat16 hb = __float2bfloat16(y);
        dsth[d] = hb;
        dstl[d] = __float2bfloat16(y - __bfloat162float(hb));
        __syncthreads();
    }
}

// ================= HMMA flash attention (sliding window + softcap) =========
#define APITCH 528
#define AQH_OFF 0
#define AQL_OFF 33792
#define AKH_OFF 67584
#define AKL_OFF 101376
#define AVH_OFF 135168
#define AVL_OFF 168960
#define APH_OFF 202752
#define APL_OFF 211968
#define ASTAT_OFF 221184
#define SMEM_ATTN 222976

__global__ __launch_bounds__(256, 1)
void attn_mma(const __nv_bfloat16* __restrict__ Qh, const __nv_bfloat16* __restrict__ Ql,
              const __nv_bfloat16* __restrict__ Kh, const __nv_bfloat16* __restrict__ Kl,
              const __nv_bfloat16* __restrict__ Vh, const __nv_bfloat16* __restrict__ Vl,
              __nv_bfloat16* __restrict__ AOh, __nv_bfloat16* __restrict__ AOl) {
    extern __shared__ char smemc[];
    const uint32_t sb = smem_u32(smemc);
    const int tid = threadIdx.x;
    const int lane = tid & 31;
    const int w = tid >> 5;
    const int h = blockIdx.y;
    const int q0 = blockIdx.x * 64;

    const __nv_bfloat16* qhp = Qh + ((size_t)h * S_LEN + q0) * HD;
    const __nv_bfloat16* qlp = Ql + ((size_t)h * S_LEN + q0) * HD;
    const __nv_bfloat16* khp = Kh + (size_t)(h >> 1) * S_LEN * HD;
    const __nv_bfloat16* klp = Kl + (size_t)(h >> 1) * S_LEN * HD;
    const __nv_bfloat16* vhp = Vh + (size_t)(h >> 1) * S_LEN * HD;
    const __nv_bfloat16* vlp = Vl + (size_t)(h >> 1) * S_LEN * HD;

    float* marr  = (float*)(smemc + ASTAT_OFF);
    float* larr  = marr + 64;
    float* alpha = marr + 128;
    float* pm0   = marr + 192;
    float* pm1   = marr + 256;
    float* ps0   = marr + 320;
    float* ps1   = marr + 384;

    if (tid < 64) { marr[tid] = -1e30f; larr[tid] = 0.f; }

    auto cpQ = [&](uint32_t off, const __nv_bfloat16* src) {
#pragma unroll
        for (int i = 0; i < 8; i++) {
            int flat = tid + i * 256;
            int r = flat >> 5, c = flat & 31;
            CP_ASYNC16(sb + off + r * APITCH + c * 16, src + (size_t)r * HD + c * 8);
        }
    };
    auto cpT = [&](uint32_t off, const __nv_bfloat16* base, int kt) {
#pragma unroll
        for (int i = 0; i < 8; i++) {
            int flat = tid + i * 256;
            int r = flat >> 5, c = flat & 31;
            CP_ASYNC16(sb + off + r * APITCH + c * 16, base + (size_t)(kt + r) * HD + c * 8);
        }
    };

    int klo = q0 - (WIN - 1);
    if (klo < 0) klo = 0;
    const int kt0 = klo & ~63;

    cpQ(AQH_OFF, qhp); cpQ(AQL_OFF, qlp);
    cpT(AKH_OFF, khp, kt0); cpT(AKL_OFF, klp, kt0);
    CP_COMMIT();

    float oacc[16][4];
#pragma unroll
    for (int i = 0; i < 16; i++)
#pragma unroll
        for (int q = 0; q < 4; q++) oacc[i][q] = 0.f;

    const int aro = (lane & 7) + 8 * ((lane >> 3) & 1);
    const int aco = (lane >> 4) * 16;
    const int bro = (lane & 7) + 8 * ((lane >> 4) & 1);
    const int bco = ((lane >> 3) & 1) * 16;
    const int R  = 16 * (w >> 1);
    const int Ch = 32 * (w & 1);
    const int Rp = 16 * (w & 3);
    const int Dq = 128 * (w >> 2);
    const int rl = lane >> 2;

    __syncthreads();

    for (int kt = kt0; kt <= q0; kt += 64) {
        cpT(AVH_OFF, vhp, kt); cpT(AVL_OFF, vlp, kt);
        CP_COMMIT();
        CP_WAIT1();
        __syncthreads();

        // ---------------- QK ----------------
        float sacc[4][4];
#pragma unroll
        for (int i = 0; i < 4; i++)
#pragma unroll
            for (int q = 0; q < 4; q++) sacc[i][q] = 0.f;

#pragma unroll
        for (int ks = 0; ks < 16; ks++) {
            uint32_t aH[4], aL[4];
            uint32_t ab = sb + AQH_OFF + (R + aro) * APITCH + ks * 32 + aco;
            ldsm4(aH, ab);
            ldsm4(aL, ab + (AQL_OFF - AQH_OFF));
            uint32_t bH0[4], bL0[4], bH1[4], bL1[4];
            uint32_t bb0 = sb + AKH_OFF + (Ch + bro) * APITCH + ks * 32 + bco;
            uint32_t bb1 = sb + AKH_OFF + (Ch + 16 + bro) * APITCH + ks * 32 + bco;
            ldsm4(bH0, bb0);
            ldsm4(bL0, bb0 + (AKL_OFF - AKH_OFF));
            ldsm4(bH1, bb1);
            ldsm4(bL1, bb1 + (AKL_OFF - AKH_OFF));
            // term-major: RAW distance 4
            mma16816(sacc[0], aH, bH0[0], bH0[1]);
            mma16816(sacc[1], aH, bH0[2], bH0[3]);
            mma16816(sacc[2], aH, bH1[0], bH1[1]);
            mma16816(sacc[3], aH, bH1[2], bH1[3]);
            mma16816(sacc[0], aH, bL0[0], bL0[1]);
            mma16816(sacc[1], aH, bL0[2], bL0[3]);
            mma16816(sacc[2], aH, bL1[0], bL1[1]);
            mma16816(sacc[3], aH, bL1[2], bL1[3]);
            mma16816(sacc[0], aL, bH0[0], bH0[1]);
            mma16816(sacc[1], aL, bH0[2], bH0[3]);
            mma16816(sacc[2], aL, bH1[0], bH1[1]);
            mma16816(sacc[3], aL, bH1[2], bH1[3]);
        }

        const int rlo = R + rl, rhi = R + rl + 8;
        float mx0 = -1e30f, mx1 = -1e30f;
#pragma unroll
        for (int n8 = 0; n8 < 4; n8++) {
#pragma unroll
            for (int e = 0; e < 4; e++) {
                int row = (e < 2) ? rlo : rhi;
                int kg = kt + Ch + n8 * 8 + (lane & 3) * 2 + (e & 1);
                int qg = q0 + row;
                float s = 50.0f * tanhf(sacc[n8][e] * 0.02f);
                bool ok = (kg <= qg) && (qg - kg < WIN);
                s = ok ? s : -1e30f;
                sacc[n8][e] = s;
                if (e < 2) mx0 = fmaxf(mx0, s); else mx1 = fmaxf(mx1, s);
            }
        }
        mx0 = fmaxf(mx0, __shfl_xor_sync(0xffffffffu, mx0, 1));
        mx0 = fmaxf(mx0, __shfl_xor_sync(0xffffffffu, mx0, 2));
        mx1 = fmaxf(mx1, __shfl_xor_sync(0xffffffffu, mx1, 1));
        mx1 = fmaxf(mx1, __shfl_xor_sync(0xffffffffu, mx1, 2));
        if ((lane & 3) == 0) {
            float* pmh = (w & 1) ? pm1 : pm0;
            pmh[rlo] = mx0; pmh[rhi] = mx1;
        }
        __syncthreads();

        if (kt + 64 <= q0) { cpT(AKH_OFF, khp, kt + 64); cpT(AKL_OFF, klp, kt + 64); }
        CP_COMMIT();

        if (tid < 64) {
            float mo = marr[tid];
            float mn = fmaxf(mo, fmaxf(pm0[tid], pm1[tid]));
            alpha[tid] = (mn > -1e29f) ? __expf(mo - mn) : 1.f;
            marr[tid] = mn;
        }
        __syncthreads();

        {
            float mn0 = marr[rlo], mn1 = marr[rhi];
            float sum0 = 0.f, sum1 = 0.f;
#pragma unroll
            for (int n8 = 0; n8 < 4; n8++) {
                float p0 = (sacc[n8][0] > -1e29f) ? __expf(sacc[n8][0] - mn0) : 0.f;
                float p1 = (sacc[n8][1] > -1e29f) ? __expf(sacc[n8][1] - mn0) : 0.f;
                float p2 = (sacc[n8][2] > -1e29f) ? __expf(sacc[n8][2] - mn1) : 0.f;
                float p3 = (sacc[n8][3] > -1e29f) ? __expf(sacc[n8][3] - mn1) : 0.f;
                sum0 += p0 + p1; sum1 += p2 + p3;
                int cb = (Ch + n8 * 8 + (lane & 3) * 2) * 2;
                uint32_t hlo = pack2bf(p0, p1);
                uint32_t hhi = pack2bf(p2, p3);
                float r0a = __bfloat162float(__nv_bfloat16(((__nv_bfloat162*)&hlo)->x));
                float r0b = __bfloat162float(__nv_bfloat16(((__nv_bfloat162*)&hlo)->y));
                float r1a = __bfloat162float(__nv_bfloat16(((__nv_bfloat162*)&hhi)->x));
                float r1b = __bfloat162float(__nv_bfloat16(((__nv_bfloat162*)&hhi)->y));
                *(uint32_t*)(smemc + APH_OFF + rlo * 144 + cb) = hlo;
                *(uint32_t*)(smemc + APH_OFF + rhi * 144 + cb) = hhi;
                *(uint32_t*)(smemc + APL_OFF + rlo * 144 + cb) = pack2bf(p0 - r0a, p1 - r0b);
                *(uint32_t*)(smemc + APL_OFF + rhi * 144 + cb) = pack2bf(p2 - r1a, p3 - r1b);
            }
            sum0 += __shfl_xor_sync(0xffffffffu, sum0, 1);
            sum0 += __shfl_xor_sync(0xffffffffu, sum0, 2);
            sum1 += __shfl_xor_sync(0xffffffffu, sum1, 1);
            sum1 += __shfl_xor_sync(0xffffffffu, sum1, 2);
            if ((lane & 3) == 0) {
                float* psh = (w & 1) ? ps1 : ps0;
                psh[rlo] = sum0; psh[rhi] = sum1;
            }
        }
        __syncthreads();
        if (tid < 64) larr[tid] = alpha[tid] * larr[tid] + ps0[tid] + ps1[tid];
        CP_WAIT1();
        __syncthreads();

        // ---------------- PV ----------------
        {
            float a0 = alpha[Rp + rl], a1 = alpha[Rp + 8 + rl];
#pragma unroll
            for (int n8 = 0; n8 < 16; n8++) {
                oacc[n8][0] *= a0; oacc[n8][1] *= a0;
                oacc[n8][2] *= a1; oacc[n8][3] *= a1;
            }
            const int vco = ((lane >> 4) & 1) * 8;
            const int vrw = (lane & 7) + 8 * ((lane >> 3) & 1);
#pragma unroll
            for (int ks = 0; ks < 4; ks++) {
                uint32_t pH[4], pL[4];
                uint32_t pb = sb + APH_OFF + (Rp + aro) * 144 + ks * 32 + aco;
                ldsm4(pH, pb);
                ldsm4(pL, pb + (APL_OFF - APH_OFF));
#pragma unroll
                for (int dt = 0; dt < 8; dt += 2) {
                    uint32_t vH0[4], vL0[4], vH1[4], vL1[4];
                    uint32_t vb0 = sb + AVH_OFF + (ks * 16 + vrw) * APITCH +
                                   (Dq + dt * 16 + vco) * 2;
                    uint32_t vb1 = vb0 + 32;   // (dt+1)*16 -> +16 cols = +32B
                    ldsm4t(vH0, vb0);
                    ldsm4t(vL0, vb0 + (AVL_OFF - AVH_OFF));
                    ldsm4t(vH1, vb1);
                    ldsm4t(vL1, vb1 + (AVL_OFF - AVH_OFF));
                    // term-major: RAW distance 4
                    mma16816(oacc[2 * dt],     pH, vH0[0], vH0[1]);
                    mma16816(oacc[2 * dt + 1], pH, vH0[2], vH0[3]);
                    mma16816(oacc[2 * dt + 2], pH, vH1[0], vH1[1]);
                    mma16816(oacc[2 * dt + 3], pH, vH1[2], vH1[3]);
                    mma16816(oacc[2 * dt],     pH, vL0[0], vL0[1]);
                    mma16816(oacc[2 * dt + 1], pH, vL0[2], vL0[3]);
                    mma16816(oacc[2 * dt + 2], pH, vL1[0], vL1[1]);
                    mma16816(oacc[2 * dt + 3], pH, vL1[2], vL1[3]);
                    mma16816(oacc[2 * dt],     pL, vH0[0], vH0[1]);
                    mma16816(oacc[2 * dt + 1], pL, vH0[2], vH0[3]);
                    mma16816(oacc[2 * dt + 2], pL, vH1[0], vH1[1]);
                    mma16816(oacc[2 * dt + 3], pL, vH1[2], vH1[3]);
                }
            }
        }
        __syncthreads();
    }

    // output: bf16 hi/lo, [S][HQ*HD]
    {
        float inv0 = 1.0f / larr[Rp + rl];
        float inv1 = 1.0f / larr[Rp + 8 + rl];
        const int r0 = q0 + Rp + rl;
#pragma unroll
        for (int n8 = 0; n8 < 16; n8++) {
            int col = h * HD + Dq + n8 * 8 + (lane & 3) * 2;
            float o0 = oacc[n8][0] * inv0, o1 = oacc[n8][1] * inv0;
            float o2 = oacc[n8][2] * inv1, o3 = oacc[n8][3] * inv1;
            uint32_t h0 = pack2bf(o0, o1);
            __nv_bfloat162 hv0 = *(__nv_bfloat162*)&h0;
            uint32_t l0 = pack2bf(o0 - __bfloat162float(hv0.x), o1 - __bfloat162float(hv0.y));
            uint32_t h1 = pack2bf(o2, o3);
            __nv_bfloat162 hv1 = *(__nv_bfloat162*)&h1;
            uint32_t l1 = pack2bf(o2 - __bfloat162float(hv1.x), o3 - __bfloat162float(hv1.y));
            *(uint32_t*)(AOh + (size_t)r0 * (HQ * HD) + col) = h0;
            *(uint32_t*)(AOl + (size_t)r0 * (HQ * HD) + col) = l0;
            *(uint32_t*)(AOh + (size_t)(r0 + 8) * (HQ * HD) + col) = h1;
            *(uint32_t*)(AOl + (size_t)(r0 + 8) * (HQ * HD) + col) = l1;
        }
    }
}

// ================= launch =================
extern "C" void kernel_launch(void* const* d_in, const int* in_sizes, int n_in,
                              void* d_out, int out_size) {
    const float* hidden = (const float*)d_in[0];
    const float* cosb   = (const float*)d_in[1];
    const float* sinb   = (const float*)d_in[2];
    // d_in[3] = attention_mask (sliding window, implemented analytically)
    const float* Wq = (const float*)d_in[4];
    const float* Wk = (const float*)d_in[5];
    const float* Wv = (const float*)d_in[6];
    const float* Wo = (const float*)d_in[7];
    const float* qw = (const float*)d_in[8];
    const float* kw = (const float*)d_in[9];
    float* out = (float*)d_out;

    float *Qp, *Kp, *Vp;
    cudaGetSymbolAddress((void**)&Qp, g_Qp);
    cudaGetSymbolAddress((void**)&Kp, g_Kp);
    cudaGetSymbolAddress((void**)&Vp, g_Vp);

    __nv_bfloat16 *hidh, *hidl, *wqh, *wql, *wkh, *wkl, *wvh, *wvl, *woh, *wol, *aoh, *aol;
    __nv_bfloat16 *qrh, *qrl, *krh, *krl, *vrh, *vrl;
    cudaGetSymbolAddress((void**)&hidh, g_hid_h);
    cudaGetSymbolAddress((void**)&hidl, g_hid_l);
    cudaGetSymbolAddress((void**)&wqh, g_wq_h);
    cudaGetSymbolAddress((void**)&wql, g_wq_l);
    cudaGetSymbolAddress((void**)&wkh, g_wk_h);
    cudaGetSymbolAddress((void**)&wkl, g_wk_l);
    cudaGetSymbolAddress((void**)&wvh, g_wv_h);
    cudaGetSymbolAddress((void**)&wvl, g_wv_l);
    cudaGetSymbolAddress((void**)&woh, g_wo_h);
    cudaGetSymbolAddress((void**)&wol, g_wo_l);
    cudaGetSymbolAddress((void**)&aoh, g_ao_h);
    cudaGetSymbolAddress((void**)&aol, g_ao_l);
    cudaGetSymbolAddress((void**)&qrh, g_qr_h);
    cudaGetSymbolAddress((void**)&qrl, g_qr_l);
    cudaGetSymbolAddress((void**)&krh, g_kr_h);
    cudaGetSymbolAddress((void**)&krl, g_kr_l);
    cudaGetSymbolAddress((void**)&vrh, g_vr_h);
    cudaGetSymbolAddress((void**)&vrl, g_vr_l);

    cudaFuncSetAttribute((const void*)gemm_bf16x3,
                         cudaFuncAttributeMaxDynamicSharedMemorySize, SMEM_GEMM);
    cudaFuncSetAttribute((const void*)attn_mma,
                         cudaFuncAttributeMaxDynamicSharedMemorySize, SMEM_ATTN);

    // fused fp32 -> bf16 hi/lo splits (all 5 tensors, one launch)
    cvt_all<<<(N4_TOT + 255) / 256, 256>>>(
        (const float4*)hidden, (const float4*)Wq, (const float4*)Wk,
        (const float4*)Wv, (const float4*)Wo,
        hidh, hidl, wqh, wql, wkh, wkl, wvh, wvl, woh, wol);

    // QKV projections (128x128 tiles, 2 CTA/SM, 3-stage)
    gemm_bf16x3<<<dim3(16, 32), 128, SMEM_GEMM>>>(hidh, hidl, wqh, wql, Qp, HQ * HD, H_DIM);
    gemm_bf16x3<<<dim3(8, 32), 128, SMEM_GEMM>>>(hidh, hidl, wkh, wkl, Kp, HKV * HD, H_DIM);
    gemm_bf16x3<<<dim3(8, 32), 128, SMEM_GEMM>>>(hidh, hidl, wvh, wvl, Vp, HKV * HD, H_DIM);

    // RMSNorm + RoPE -> bf16 hi/lo head-major
    norm_rope2<<<S_LEN, 256>>>(Qp, Kp, Vp, cosb, sinb, qw, kw,
                               qrh, qrl, krh, krl, vrh, vrl);

    // tensor-core flash attention -> bf16 hi/lo directly
    attn_mma<<<dim3(S_LEN / 64, HQ), 256, SMEM_ATTN>>>(qrh, qrl, krh, krl, vrh, vrl, aoh, aol);

    // output projection
    gemm_bf16x3<<<dim3(16, 32), 128, SMEM_GEMM>>>(aoh, aol, woh, wol, out, H_DIM, H_DIM);
}

// round 11
// speedup vs baseline: 1.0607x; 1.0607x over previous
#include <cuda_runtime.h>
#include <cuda_bf16.h>
#include <math.h>
#include <stdint.h>

#define S_LEN 4096
#define H_DIM 2048
#define HQ 8
#define HKV 4
#define HD 256
#define WIN 1024

// ================= portable PTX helpers (baseline ISA only) =================
__device__ __forceinline__ uint32_t smem_u32(const void* p) {
    uint32_t a;
    asm("{ .reg .u64 t; cvta.to.shared.u64 t, %1; cvt.u32.u64 %0, t; }"
        : "=r"(a) : "l"(p));
    return a;
}

#define CP_ASYNC16(dst_u32, src_ptr) \
    asm volatile("cp.async.cg.shared.global [%0], [%1], 16;" \
                 :: "r"(dst_u32), "l"(src_ptr) : "memory")
#define CP_COMMIT() asm volatile("cp.async.commit_group;" ::: "memory")
#define CP_WAIT1()  asm volatile("cp.async.wait_group 1;" ::: "memory")

__device__ __forceinline__ void mma16816(float* d, const uint32_t* a,
                                         uint32_t b0, uint32_t b1) {
    asm volatile(
        "mma.sync.aligned.m16n8k16.row.col.f32.bf16.bf16.f32 "
        "{%0,%1,%2,%3}, {%4,%5,%6,%7}, {%8,%9}, {%0,%1,%2,%3};"
        : "+f"(d[0]), "+f"(d[1]), "+f"(d[2]), "+f"(d[3])
        : "r"(a[0]), "r"(a[1]), "r"(a[2]), "r"(a[3]), "r"(b0), "r"(b1));
}

__device__ __forceinline__ void ldsm4(uint32_t* r, uint32_t addr) {
    asm volatile("ldmatrix.sync.aligned.m8n8.x4.shared.b16 {%0,%1,%2,%3}, [%4];"
                 : "=r"(r[0]), "=r"(r[1]), "=r"(r[2]), "=r"(r[3]) : "r"(addr));
}
__device__ __forceinline__ void ldsm4t(uint32_t* r, uint32_t addr) {
    asm volatile("ldmatrix.sync.aligned.m8n8.x4.trans.shared.b16 {%0,%1,%2,%3}, [%4];"
                 : "=r"(r[0]), "=r"(r[1]), "=r"(r[2]), "=r"(r[3]) : "r"(addr));
}

__device__ __forceinline__ uint32_t pack2bf(float a, float b) {
    __nv_bfloat162 t = __floats2bfloat162_rn(a, b);
    return *(uint32_t*)&t;
}

// ================= scratch (device globals) =================
__device__ float g_Qp[S_LEN * (HQ * HD)];
__device__ float g_Kp[S_LEN * (HKV * HD)];
__device__ float g_Vp[S_LEN * (HKV * HD)];

__device__ __nv_bfloat16 g_hid_h[S_LEN * H_DIM];
__device__ __nv_bfloat16 g_hid_l[S_LEN * H_DIM];
__device__ __nv_bfloat16 g_wq_h[HQ * HD * H_DIM];
__device__ __nv_bfloat16 g_wq_l[HQ * HD * H_DIM];
__device__ __nv_bfloat16 g_wk_h[HKV * HD * H_DIM];
__device__ __nv_bfloat16 g_wk_l[HKV * HD * H_DIM];
__device__ __nv_bfloat16 g_wv_h[HKV * HD * H_DIM];
__device__ __nv_bfloat16 g_wv_l[HKV * HD * H_DIM];
__device__ __nv_bfloat16 g_wo_h[H_DIM * HQ * HD];
__device__ __nv_bfloat16 g_wo_l[H_DIM * HQ * HD];
__device__ __nv_bfloat16 g_ao_h[S_LEN * HQ * HD];
__device__ __nv_bfloat16 g_ao_l[S_LEN * HQ * HD];

__device__ __nv_bfloat16 g_qr_h[HQ * S_LEN * HD];
__device__ __nv_bfloat16 g_qr_l[HQ * S_LEN * HD];
__device__ __nv_bfloat16 g_kr_h[HKV * S_LEN * HD];
__device__ __nv_bfloat16 g_kr_l[HKV * S_LEN * HD];
__device__ __nv_bfloat16 g_vr_h[HKV * S_LEN * HD];
__device__ __nv_bfloat16 g_vr_l[HKV * S_LEN * HD];

// ================= fused fp32 -> bf16 hi/lo split (all 5 tensors) ==========
#define N4_HID (S_LEN * H_DIM / 4)
#define N4_WQ  (HQ * HD * H_DIM / 4)
#define N4_WK  (HKV * HD * H_DIM / 4)
#define N4_WV  (HKV * HD * H_DIM / 4)
#define N4_WO  (H_DIM * HQ * HD / 4)
#define N4_TOT (N4_HID + N4_WQ + N4_WK + N4_WV + N4_WO)

__global__ __launch_bounds__(256)
void cvt_all(const float4* __restrict__ hid, const float4* __restrict__ wq,
             const float4* __restrict__ wk, const float4* __restrict__ wv,
             const float4* __restrict__ wo,
             __nv_bfloat16* __restrict__ hidh, __nv_bfloat16* __restrict__ hidl,
             __nv_bfloat16* __restrict__ wqh,  __nv_bfloat16* __restrict__ wql,
             __nv_bfloat16* __restrict__ wkh,  __nv_bfloat16* __restrict__ wkl,
             __nv_bfloat16* __restrict__ wvh,  __nv_bfloat16* __restrict__ wvl,
             __nv_bfloat16* __restrict__ woh,  __nv_bfloat16* __restrict__ wol) {
    int i = blockIdx.x * blockDim.x + threadIdx.x;
    if (i >= N4_TOT) return;
    const float4* src;
    __nv_bfloat16 *hi, *lo;
    int j = i;
    if (j < N4_HID) { src = hid; hi = hidh; lo = hidl; }
    else if ((j -= N4_HID) < N4_WQ) { src = wq; hi = wqh; lo = wql; }
    else if ((j -= N4_WQ) < N4_WK)  { src = wk; hi = wkh; lo = wkl; }
    else if ((j -= N4_WK) < N4_WV)  { src = wv; hi = wvh; lo = wvl; }
    else { j -= N4_WV; src = wo; hi = woh; lo = wol; }
    float4 v = src[j];
    union { ushort4 u; __nv_bfloat16 b[4]; } H, L;
    H.b[0] = __float2bfloat16(v.x);
    H.b[1] = __float2bfloat16(v.y);
    H.b[2] = __float2bfloat16(v.z);
    H.b[3] = __float2bfloat16(v.w);
    L.b[0] = __float2bfloat16(v.x - __bfloat162float(H.b[0]));
    L.b[1] = __float2bfloat16(v.y - __bfloat162float(H.b[1]));
    L.b[2] = __float2bfloat16(v.z - __bfloat162float(H.b[2]));
    L.b[3] = __float2bfloat16(v.w - __bfloat162float(H.b[3]));
    *(ushort4*)(hi + 4 * (size_t)j) = H.u;
    *(ushort4*)(lo + 4 * (size_t)j) = L.u;
}

// ================= HMMA bf16x3 GEMM: C[M,N] = A[M,K] @ B[N,K]^T ============
// CTA 64x128, 128 threads (4 warps 2x2), warp tile 32x64, BK=32.
// 3-stage cp.async ring, XOR-swizzled smem, 3 CTAs/SM (12 warps, 3/SMSP).
#define G_MATA 4096                // 64 rows x 64B
#define G_MATB 8192                // 128 rows x 64B
#define G_A_H 0
#define G_A_L 4096
#define G_B_H 8192
#define G_B_L 16384
#define G_SS  24576                // one stage
#define SMEM_GEMM (3 * G_SS)

__device__ __forceinline__ uint32_t gsw(int r, int c) {   // c = 16B chunk 0..3
    return (uint32_t)(r * 64 + ((c ^ (r & 3)) * 16));
}

__global__ __launch_bounds__(128, 3)
void gemm_bf16x3(const __nv_bfloat16* __restrict__ Ah, const __nv_bfloat16* __restrict__ Al,
                 const __nv_bfloat16* __restrict__ Bh, const __nv_bfloat16* __restrict__ Bl,
                 float* __restrict__ C, int N, int K) {
    extern __shared__ char smemc[];
    const uint32_t sb = smem_u32(smemc);
    const int tid = threadIdx.x;
    const int lane = tid & 31;
    const int w = tid >> 5;
    const int wm = (w >> 1) * 32;       // 2 warp rows of 32
    const int wn = (w & 1) * 64;        // 2 warp cols of 64
    const int bm = blockIdx.y * 64;
    const int bn = blockIdx.x * 128;
    const int nkb = K / 32;

    auto load_stage = [&](int s, int kblk) {
        const uint32_t st = sb + s * G_SS;
        // A hi/lo: 64 rows x 64B each
#pragma unroll
        for (int m = 0; m < 2; m++) {
            const __nv_bfloat16* src = (m ? Al : Ah) + (size_t)bm * K + kblk;
            const uint32_t dstb = st + G_A_H + m * G_MATA;
#pragma unroll
            for (int i = 0; i < 2; i++) {
                int flat = tid + i * 128;
                int r = flat >> 2, c = flat & 3;
                CP_ASYNC16(dstb + gsw(r, c), src + (size_t)r * K + c * 8);
            }
        }
        // B hi/lo: 128 rows x 64B each
#pragma unroll
        for (int m = 0; m < 2; m++) {
            const __nv_bfloat16* src = (m ? Bl : Bh) + (size_t)bn * K + kblk;
            const uint32_t dstb = st + G_B_H + m * G_MATB;
#pragma unroll
            for (int i = 0; i < 4; i++) {
                int flat = tid + i * 128;
                int r = flat >> 2, c = flat & 3;
                CP_ASYNC16(dstb + gsw(r, c), src + (size_t)r * K + c * 8);
            }
        }
    };

    float acc[2][8][4];
#pragma unroll
    for (int i = 0; i < 2; i++)
#pragma unroll
        for (int j = 0; j < 8; j++)
#pragma unroll
            for (int q = 0; q < 4; q++) acc[i][j][q] = 0.f;

    load_stage(0, 0);  CP_COMMIT();
    load_stage(1, 32); CP_COMMIT();
    load_stage(2, 64); CP_COMMIT();

    const int aro = (lane & 7) + 8 * ((lane >> 3) & 1);
    const int acs = (lane >> 4);
    const int bro = (lane & 7) + 8 * ((lane >> 4) & 1);
    const int bcs = ((lane >> 3) & 1);

    int s = 0;
    for (int kb = 0; kb < nkb; kb++) {
        CP_WAIT1();
        __syncthreads();
        if (kb >= 1 && kb + 2 < nkb) load_stage((kb + 2) % 3, (kb + 2) * 32);
        if (kb >= 1) CP_COMMIT();
        const uint32_t st = sb + s * G_SS;

#pragma unroll
        for (int kk = 0; kk < 2; kk++) {
            uint32_t ah[2][4], al[2][4];
#pragma unroll
            for (int i = 0; i < 2; i++) {
                int r = wm + i * 16 + aro;
                uint32_t ab = st + G_A_H + gsw(r, kk * 2 + acs);
                ldsm4(ah[i], ab);
                ldsm4(al[i], ab + G_MATA);
            }
#pragma unroll
            for (int jp = 0; jp < 4; jp++) {
                uint32_t bh[4], bl[4];
                int r = wn + jp * 16 + bro;
                uint32_t bb = st + G_B_H + gsw(r, kk * 2 + bcs);
                ldsm4(bh, bb);
                ldsm4(bl, bb + G_MATB);
#pragma unroll
                for (int i = 0; i < 2; i++) {
                    mma16816(acc[i][2 * jp],     ah[i], bh[0], bh[1]);
                    mma16816(acc[i][2 * jp + 1], ah[i], bh[2], bh[3]);
                }
#pragma unroll
                for (int i = 0; i < 2; i++) {
                    mma16816(acc[i][2 * jp],     ah[i], bl[0], bl[1]);
                    mma16816(acc[i][2 * jp + 1], ah[i], bl[2], bl[3]);
                }
#pragma unroll
                for (int i = 0; i < 2; i++) {
                    mma16816(acc[i][2 * jp],     al[i], bh[0], bh[1]);
                    mma16816(acc[i][2 * jp + 1], al[i], bh[2], bh[3]);
                }
            }
        }
        s = (s == 2) ? 0 : s + 1;
    }

    const int lr = lane >> 2;
    const int lc = lane & 3;
#pragma unroll
    for (int i = 0; i < 2; i++) {
        const int r0 = bm + wm + i * 16 + lr;
#pragma unroll
        for (int j = 0; j < 8; j++) {
            const int c0 = bn + wn + j * 8 + lc * 2;
            *(float2*)(C + (size_t)r0 * N + c0) = make_float2(acc[i][j][0], acc[i][j][1]);
            *(float2*)(C + (size_t)(r0 + 8) * N + c0) = make_float2(acc[i][j][2], acc[i][j][3]);
        }
    }
}

// ======= RMSNorm + RoPE -> bf16 hi/lo head-major (1 block per position) =====
__global__ __launch_bounds__(256)
void norm_rope2(const float* __restrict__ Qp, const float* __restrict__ Kp,
                const float* __restrict__ Vp,
                const float* __restrict__ cosb, const float* __restrict__ sinb,
                const float* __restrict__ qw, const float* __restrict__ kw,
                __nv_bfloat16* __restrict__ Qrh, __nv_bfloat16* __restrict__ Qrl,
                __nv_bfloat16* __restrict__ Krh, __nv_bfloat16* __restrict__ Krl,
                __nv_bfloat16* __restrict__ Vrh, __nv_bfloat16* __restrict__ Vrl) {
    const int s = blockIdx.x;
    const int d = threadIdx.x;

    __shared__ float cs[HD], sn[HD], qws[HD], kws[HD], red[8], ysh[HD];
    cs[d]  = cosb[(size_t)s * HD + d];
    sn[d]  = sinb[(size_t)s * HD + d];
    qws[d] = qw[d];
    kws[d] = kw[d];
    __syncthreads();

    for (int hh = 0; hh < HQ + 2 * HKV; hh++) {
        const float* src;
        __nv_bfloat16 *dsth, *dstl;
        const float* wv = nullptr;
        bool do_rope = false;

        if (hh < HQ) {
            src = Qp + (size_t)s * (HQ * HD) + hh * HD;
            dsth = Qrh + ((size_t)hh * S_LEN + s) * HD;
            dstl = Qrl + ((size_t)hh * S_LEN + s) * HD;
            wv = qws; do_rope = true;
        } else if (hh < HQ + HKV) {
            int h = hh - HQ;
            src = Kp + (size_t)s * (HKV * HD) + h * HD;
            dsth = Krh + ((size_t)h * S_LEN + s) * HD;
            dstl = Krl + ((size_t)h * S_LEN + s) * HD;
            wv = kws; do_rope = true;
        } else {
            int h = hh - HQ - HKV;
            src = Vp + (size_t)s * (HKV * HD) + h * HD;
            dsth = Vrh + ((size_t)h * S_LEN + s) * HD;
            dstl = Vrl + ((size_t)h * S_LEN + s) * HD;
        }

        float x = src[d];
        float v = x * x;
#pragma unroll
        for (int off = 16; off > 0; off >>= 1)
            v += __shfl_xor_sync(0xffffffffu, v, off);
        if ((d & 31) == 0) red[d >> 5] = v;
        __syncthreads();
        float tot = 0.f;
#pragma unroll
        for (int r = 0; r < 8; r++) tot += red[r];

        float rms = rsqrtf(tot * (1.0f / HD) + 1e-6f);
        float y = x * rms;
        if (wv) y *= wv[d];

        if (do_rope) {
            ysh[d] = y;
            __syncthreads();
            float rot = (d < HD / 2) ? -ysh[d + HD / 2] : ysh[d - HD / 2];
            y = y * cs[d] + rot * sn[d];
        }
        __nv_bfloat16 hb = __float2bfloat16(y);
        dsth[d] = hb;
        dstl[d] = __float2bfloat16(y - __bfloat162float(hb));
        __syncthreads();
    }
}

// ================= HMMA flash attention (sliding window + softcap) =========
#define APITCH 528
#define AQH_OFF 0
#define AQL_OFF 33792
#define AKH_OFF 67584
#define AKL_OFF 101376
#define AVH_OFF 135168
#define AVL_OFF 168960
#define APH_OFF 202752
#define APL_OFF 211968
#define ASTAT_OFF 221184
#define SMEM_ATTN 222976

__global__ __launch_bounds__(256, 1)
void attn_mma(const __nv_bfloat16* __restrict__ Qh, const __nv_bfloat16* __restrict__ Ql,
              const __nv_bfloat16* __restrict__ Kh, const __nv_bfloat16* __restrict__ Kl,
              const __nv_bfloat16* __restrict__ Vh, const __nv_bfloat16* __restrict__ Vl,
              __nv_bfloat16* __restrict__ AOh, __nv_bfloat16* __restrict__ AOl) {
    extern __shared__ char smemc[];
    const uint32_t sb = smem_u32(smemc);
    const int tid = threadIdx.x;
    const int lane = tid & 31;
    const int w = tid >> 5;
    const int h = blockIdx.y;
    const int q0 = blockIdx.x * 64;

    const __nv_bfloat16* qhp = Qh + ((size_t)h * S_LEN + q0) * HD;
    const __nv_bfloat16* qlp = Ql + ((size_t)h * S_LEN + q0) * HD;
    const __nv_bfloat16* khp = Kh + (size_t)(h >> 1) * S_LEN * HD;
    const __nv_bfloat16* klp = Kl + (size_t)(h >> 1) * S_LEN * HD;
    const __nv_bfloat16* vhp = Vh + (size_t)(h >> 1) * S_LEN * HD;
    const __nv_bfloat16* vlp = Vl + (size_t)(h >> 1) * S_LEN * HD;

    float* marr  = (float*)(smemc + ASTAT_OFF);
    float* larr  = marr + 64;
    float* alpha = marr + 128;
    float* pm0   = marr + 192;
    float* pm1   = marr + 256;
    float* ps0   = marr + 320;
    float* ps1   = marr + 384;

    if (tid < 64) { marr[tid] = -1e30f; larr[tid] = 0.f; }

    auto cpQ = [&](uint32_t off, const __nv_bfloat16* src) {
#pragma unroll
        for (int i = 0; i < 8; i++) {
            int flat = tid + i * 256;
            int r = flat >> 5, c = flat & 31;
            CP_ASYNC16(sb + off + r * APITCH + c * 16, src + (size_t)r * HD + c * 8);
        }
    };
    auto cpT = [&](uint32_t off, const __nv_bfloat16* base, int kt) {
#pragma unroll
        for (int i = 0; i < 8; i++) {
            int flat = tid + i * 256;
            int r = flat >> 5, c = flat & 31;
            CP_ASYNC16(sb + off + r * APITCH + c * 16, base + (size_t)(kt + r) * HD + c * 8);
        }
    };

    int klo = q0 - (WIN - 1);
    if (klo < 0) klo = 0;
    const int kt0 = klo & ~63;

    cpQ(AQH_OFF, qhp); cpQ(AQL_OFF, qlp);
    cpT(AKH_OFF, khp, kt0); cpT(AKL_OFF, klp, kt0);
    CP_COMMIT();

    float oacc[16][4];
#pragma unroll
    for (int i = 0; i < 16; i++)
#pragma unroll
        for (int q = 0; q < 4; q++) oacc[i][q] = 0.f;

    const int aro = (lane & 7) + 8 * ((lane >> 3) & 1);
    const int aco = (lane >> 4) * 16;
    const int bro = (lane & 7) + 8 * ((lane >> 4) & 1);
    const int bco = ((lane >> 3) & 1) * 16;
    const int R  = 16 * (w >> 1);
    const int Ch = 32 * (w & 1);
    const int Rp = 16 * (w & 3);
    const int Dq = 128 * (w >> 2);
    const int rl = lane >> 2;

    __syncthreads();

    for (int kt = kt0; kt <= q0; kt += 64) {
        cpT(AVH_OFF, vhp, kt); cpT(AVL_OFF, vlp, kt);
        CP_COMMIT();
        CP_WAIT1();
        __syncthreads();

        // ---------------- QK ----------------
        float sacc[4][4];
#pragma unroll
        for (int i = 0; i < 4; i++)
#pragma unroll
            for (int q = 0; q < 4; q++) sacc[i][q] = 0.f;

#pragma unroll
        for (int ks = 0; ks < 16; ks++) {
            uint32_t aH[4], aL[4];
            uint32_t ab = sb + AQH_OFF + (R + aro) * APITCH + ks * 32 + aco;
            ldsm4(aH, ab);
            ldsm4(aL, ab + (AQL_OFF - AQH_OFF));
            uint32_t bH0[4], bL0[4], bH1[4], bL1[4];
            uint32_t bb0 = sb + AKH_OFF + (Ch + bro) * APITCH + ks * 32 + bco;
            uint32_t bb1 = sb + AKH_OFF + (Ch + 16 + bro) * APITCH + ks * 32 + bco;
            ldsm4(bH0, bb0);
            ldsm4(bL0, bb0 + (AKL_OFF - AKH_OFF));
            ldsm4(bH1, bb1);
            ldsm4(bL1, bb1 + (AKL_OFF - AKH_OFF));
            mma16816(sacc[0], aH, bH0[0], bH0[1]);
            mma16816(sacc[1], aH, bH0[2], bH0[3]);
            mma16816(sacc[2], aH, bH1[0], bH1[1]);
            mma16816(sacc[3], aH, bH1[2], bH1[3]);
            mma16816(sacc[0], aH, bL0[0], bL0[1]);
            mma16816(sacc[1], aH, bL0[2], bL0[3]);
            mma16816(sacc[2], aH, bL1[0], bL1[1]);
            mma16816(sacc[3], aH, bL1[2], bL1[3]);
            mma16816(sacc[0], aL, bH0[0], bH0[1]);
            mma16816(sacc[1], aL, bH0[2], bH0[3]);
            mma16816(sacc[2], aL, bH1[0], bH1[1]);
            mma16816(sacc[3], aL, bH1[2], bH1[3]);
        }

        const int rlo = R + rl, rhi = R + rl + 8;
        float mx0 = -1e30f, mx1 = -1e30f;
#pragma unroll
        for (int n8 = 0; n8 < 4; n8++) {
#pragma unroll
            for (int e = 0; e < 4; e++) {
                int row = (e < 2) ? rlo : rhi;
                int kg = kt + Ch + n8 * 8 + (lane & 3) * 2 + (e & 1);
                int qg = q0 + row;
                float s = 50.0f * tanhf(sacc[n8][e] * 0.02f);
                bool ok = (kg <= qg) && (qg - kg < WIN);
                s = ok ? s : -1e30f;
                sacc[n8][e] = s;
                if (e < 2) mx0 = fmaxf(mx0, s); else mx1 = fmaxf(mx1, s);
            }
        }
        mx0 = fmaxf(mx0, __shfl_xor_sync(0xffffffffu, mx0, 1));
        mx0 = fmaxf(mx0, __shfl_xor_sync(0xffffffffu, mx0, 2));
        mx1 = fmaxf(mx1, __shfl_xor_sync(0xffffffffu, mx1, 1));
        mx1 = fmaxf(mx1, __shfl_xor_sync(0xffffffffu, mx1, 2));
        if ((lane & 3) == 0) {
            float* pmh = (w & 1) ? pm1 : pm0;
            pmh[rlo] = mx0; pmh[rhi] = mx1;
        }
        __syncthreads();

        if (kt + 64 <= q0) { cpT(AKH_OFF, khp, kt + 64); cpT(AKL_OFF, klp, kt + 64); }
        CP_COMMIT();

        if (tid < 64) {
            float mo = marr[tid];
            float mn = fmaxf(mo, fmaxf(pm0[tid], pm1[tid]));
            alpha[tid] = (mn > -1e29f) ? __expf(mo - mn) : 1.f;
            marr[tid] = mn;
        }
        __syncthreads();

        {
            float mn0 = marr[rlo], mn1 = marr[rhi];
            float sum0 = 0.f, sum1 = 0.f;
#pragma unroll
            for (int n8 = 0; n8 < 4; n8++) {
                float p0 = (sacc[n8][0] > -1e29f) ? __expf(sacc[n8][0] - mn0) : 0.f;
                float p1 = (sacc[n8][1] > -1e29f) ? __expf(sacc[n8][1] - mn0) : 0.f;
                float p2 = (sacc[n8][2] > -1e29f) ? __expf(sacc[n8][2] - mn1) : 0.f;
                float p3 = (sacc[n8][3] > -1e29f) ? __expf(sacc[n8][3] - mn1) : 0.f;
                sum0 += p0 + p1; sum1 += p2 + p3;
                int cb = (Ch + n8 * 8 + (lane & 3) * 2) * 2;
                uint32_t hlo = pack2bf(p0, p1);
                uint32_t hhi = pack2bf(p2, p3);
                float r0a = __bfloat162float(__nv_bfloat16(((__nv_bfloat162*)&hlo)->x));
                float r0b = __bfloat162float(__nv_bfloat16(((__nv_bfloat162*)&hlo)->y));
                float r1a = __bfloat162float(__nv_bfloat16(((__nv_bfloat162*)&hhi)->x));
                float r1b = __bfloat162float(__nv_bfloat16(((__nv_bfloat162*)&hhi)->y));
                *(uint32_t*)(smemc + APH_OFF + rlo * 144 + cb) = hlo;
                *(uint32_t*)(smemc + APH_OFF + rhi * 144 + cb) = hhi;
                *(uint32_t*)(smemc + APL_OFF + rlo * 144 + cb) = pack2bf(p0 - r0a, p1 - r0b);
                *(uint32_t*)(smemc + APL_OFF + rhi * 144 + cb) = pack2bf(p2 - r1a, p3 - r1b);
            }
            sum0 += __shfl_xor_sync(0xffffffffu, sum0, 1);
            sum0 += __shfl_xor_sync(0xffffffffu, sum0, 2);
            sum1 += __shfl_xor_sync(0xffffffffu, sum1, 1);
            sum1 += __shfl_xor_sync(0xffffffffu, sum1, 2);
            if ((lane & 3) == 0) {
                float* psh = (w & 1) ? ps1 : ps0;
                psh[rlo] = sum0; psh[rhi] = sum1;
            }
        }
        __syncthreads();
        if (tid < 64) larr[tid] = alpha[tid] * larr[tid] + ps0[tid] + ps1[tid];
        CP_WAIT1();
        __syncthreads();

        // ---------------- PV ----------------
        {
            float a0 = alpha[Rp + rl], a1 = alpha[Rp + 8 + rl];
#pragma unroll
            for (int n8 = 0; n8 < 16; n8++) {
                oacc[n8][0] *= a0; oacc[n8][1] *= a0;
                oacc[n8][2] *= a1; oacc[n8][3] *= a1;
            }
            const int vco = ((lane >> 4) & 1) * 8;
            const int vrw = (lane & 7) + 8 * ((lane >> 3) & 1);
#pragma unroll
            for (int ks = 0; ks < 4; ks++) {
                uint32_t pH[4], pL[4];
                uint32_t pb = sb + APH_OFF + (Rp + aro) * 144 + ks * 32 + aco;
                ldsm4(pH, pb);
                ldsm4(pL, pb + (APL_OFF - APH_OFF));
#pragma unroll
                for (int dt = 0; dt < 8; dt += 2) {
                    uint32_t vH0[4], vL0[4], vH1[4], vL1[4];
                    uint32_t vb0 = sb + AVH_OFF + (ks * 16 + vrw) * APITCH +
                                   (Dq + dt * 16 + vco) * 2;
                    uint32_t vb1 = vb0 + 32;
                    ldsm4t(vH0, vb0);
                    ldsm4t(vL0, vb0 + (AVL_OFF - AVH_OFF));
                    ldsm4t(vH1, vb1);
                    ldsm4t(vL1, vb1 + (AVL_OFF - AVH_OFF));
                    mma16816(oacc[2 * dt],     pH, vH0[0], vH0[1]);
                    mma16816(oacc[2 * dt + 1], pH, vH0[2], vH0[3]);
                    mma16816(oacc[2 * dt + 2], pH, vH1[0], vH1[1]);
                    mma16816(oacc[2 * dt + 3], pH, vH1[2], vH1[3]);
                    mma16816(oacc[2 * dt],     pH, vL0[0], vL0[1]);
                    mma16816(oacc[2 * dt + 1], pH, vL0[2], vL0[3]);
                    mma16816(oacc[2 * dt + 2], pH, vL1[0], vL1[1]);
                    mma16816(oacc[2 * dt + 3], pH, vL1[2], vL1[3]);
                    mma16816(oacc[2 * dt],     pL, vH0[0], vH0[1]);
                    mma16816(oacc[2 * dt + 1], pL, vH0[2], vH0[3]);
                    mma16816(oacc[2 * dt + 2], pL, vH1[0], vH1[1]);
                    mma16816(oacc[2 * dt + 3], pL, vH1[2], vH1[3]);
                }
            }
        }
        __syncthreads();
    }

    // output: bf16 hi/lo, [S][HQ*HD]
    {
        float inv0 = 1.0f / larr[Rp + rl];
        float inv1 = 1.0f / larr[Rp + 8 + rl];
        const int r0 = q0 + Rp + rl;
#pragma unroll
        for (int n8 = 0; n8 < 16; n8++) {
            int col = h * HD + Dq + n8 * 8 + (lane & 3) * 2;
            float o0 = oacc[n8][0] * inv0, o1 = oacc[n8][1] * inv0;
            float o2 = oacc[n8][2] * inv1, o3 = oacc[n8][3] * inv1;
            uint32_t h0 = pack2bf(o0, o1);
            __nv_bfloat162 hv0 = *(__nv_bfloat162*)&h0;
            uint32_t l0 = pack2bf(o0 - __bfloat162float(hv0.x), o1 - __bfloat162float(hv0.y));
            uint32_t h1 = pack2bf(o2, o3);
            __nv_bfloat162 hv1 = *(__nv_bfloat162*)&h1;
            uint32_t l1 = pack2bf(o2 - __bfloat162float(hv1.x), o3 - __bfloat162float(hv1.y));
            *(uint32_t*)(AOh + (size_t)r0 * (HQ * HD) + col) = h0;
            *(uint32_t*)(AOl + (size_t)r0 * (HQ * HD) + col) = l0;
            *(uint32_t*)(AOh + (size_t)(r0 + 8) * (HQ * HD) + col) = h1;
            *(uint32_t*)(AOl + (size_t)(r0 + 8) * (HQ * HD) + col) = l1;
        }
    }
}

// ================= launch =================
extern "C" void kernel_launch(void* const* d_in, const int* in_sizes, int n_in,
                              void* d_out, int out_size) {
    const float* hidden = (const float*)d_in[0];
    const float* cosb   = (const float*)d_in[1];
    const float* sinb   = (const float*)d_in[2];
    // d_in[3] = attention_mask (sliding window, implemented analytically)
    const float* Wq = (const float*)d_in[4];
    const float* Wk = (const float*)d_in[5];
    const float* Wv = (const float*)d_in[6];
    const float* Wo = (const float*)d_in[7];
    const float* qw = (const float*)d_in[8];
    const float* kw = (const float*)d_in[9];
    float* out = (float*)d_out;

    float *Qp, *Kp, *Vp;
    cudaGetSymbolAddress((void**)&Qp, g_Qp);
    cudaGetSymbolAddress((void**)&Kp, g_Kp);
    cudaGetSymbolAddress((void**)&Vp, g_Vp);

    __nv_bfloat16 *hidh, *hidl, *wqh, *wql, *wkh, *wkl, *wvh, *wvl, *woh, *wol, *aoh, *aol;
    __nv_bfloat16 *qrh, *qrl, *krh, *krl, *vrh, *vrl;
    cudaGetSymbolAddress((void**)&hidh, g_hid_h);
    cudaGetSymbolAddress((void**)&hidl, g_hid_l);
    cudaGetSymbolAddress((void**)&wqh, g_wq_h);
    cudaGetSymbolAddress((void**)&wql, g_wq_l);
    cudaGetSymbolAddress((void**)&wkh, g_wk_h);
    cudaGetSymbolAddress((void**)&wkl, g_wk_l);
    cudaGetSymbolAddress((void**)&wvh, g_wv_h);
    cudaGetSymbolAddress((void**)&wvl, g_wv_l);
    cudaGetSymbolAddress((void**)&woh, g_wo_h);
    cudaGetSymbolAddress((void**)&wol, g_wo_l);
    cudaGetSymbolAddress((void**)&aoh, g_ao_h);
    cudaGetSymbolAddress((void**)&aol, g_ao_l);
    cudaGetSymbolAddress((void**)&qrh, g_qr_h);
    cudaGetSymbolAddress((void**)&qrl, g_qr_l);
    cudaGetSymbolAddress((void**)&krh, g_kr_h);
    cudaGetSymbolAddress((void**)&krl, g_kr_l);
    cudaGetSymbolAddress((void**)&vrh, g_vr_h);
    cudaGetSymbolAddress((void**)&vrl, g_vr_l);

    cudaFuncSetAttribute((const void*)gemm_bf16x3,
                         cudaFuncAttributeMaxDynamicSharedMemorySize, SMEM_GEMM);
    cudaFuncSetAttribute((const void*)attn_mma,
                         cudaFuncAttributeMaxDynamicSharedMemorySize, SMEM_ATTN);

    // fused fp32 -> bf16 hi/lo splits (all 5 tensors, one launch)
    cvt_all<<<(N4_TOT + 255) / 256, 256>>>(
        (const float4*)hidden, (const float4*)Wq, (const float4*)Wk,
        (const float4*)Wv, (const float4*)Wo,
        hidh, hidl, wqh, wql, wkh, wkl, wvh, wvl, woh, wol);

    // QKV projections (64x128 tiles, 3 CTA/SM, 3-stage)
    gemm_bf16x3<<<dim3(16, 64), 128, SMEM_GEMM>>>(hidh, hidl, wqh, wql, Qp, HQ * HD, H_DIM);
    gemm_bf16x3<<<dim3(8, 64), 128, SMEM_GEMM>>>(hidh, hidl, wkh, wkl, Kp, HKV * HD, H_DIM);
    gemm_bf16x3<<<dim3(8, 64), 128, SMEM_GEMM>>>(hidh, hidl, wvh, wvl, Vp, HKV * HD, H_DIM);

    // RMSNorm + RoPE -> bf16 hi/lo head-major
    norm_rope2<<<S_LEN, 256>>>(Qp, Kp, Vp, cosb, sinb, qw, kw,
                               qrh, qrl, krh, krl, vrh, vrl);

    // tensor-core flash attention -> bf16 hi/lo directly
    attn_mma<<<dim3(S_LEN / 64, HQ), 256, SMEM_ATTN>>>(qrh, qrl, krh, krl, vrh, vrl, aoh, aol);

    // output projection
    gemm_bf16x3<<<dim3(16, 64), 128, SMEM_GEMM>>>(aoh, aol, woh, wol, out, H_DIM, H_DIM);
}

// round 12
// speedup vs baseline: 1.1516x; 1.0857x over previous
#include <cuda_runtime.h>
#include <cuda_bf16.h>
#include <cuda_fp16.h>
#include <math.h>
#include <stdint.h>

#define S_LEN 4096
#define H_DIM 2048
#define HQ 8
#define HKV 4
#define HD 256
#define WIN 1024

// ================= portable PTX helpers (baseline ISA only) =================
__device__ __forceinline__ uint32_t smem_u32(const void* p) {
    uint32_t a;
    asm("{ .reg .u64 t; cvta.to.shared.u64 t, %1; cvt.u32.u64 %0, t; }"
        : "=r"(a) : "l"(p));
    return a;
}

#define CP_ASYNC16(dst_u32, src_ptr) \
    asm volatile("cp.async.cg.shared.global [%0], [%1], 16;" \
                 :: "r"(dst_u32), "l"(src_ptr) : "memory")
#define CP_COMMIT() asm volatile("cp.async.commit_group;" ::: "memory")
#define CP_WAIT1()  asm volatile("cp.async.wait_group 1;" ::: "memory")

__device__ __forceinline__ void mma16816(float* d, const uint32_t* a,
                                         uint32_t b0, uint32_t b1) {
    asm volatile(
        "mma.sync.aligned.m16n8k16.row.col.f32.bf16.bf16.f32 "
        "{%0,%1,%2,%3}, {%4,%5,%6,%7}, {%8,%9}, {%0,%1,%2,%3};"
        : "+f"(d[0]), "+f"(d[1]), "+f"(d[2]), "+f"(d[3])
        : "r"(a[0]), "r"(a[1]), "r"(a[2]), "r"(a[3]), "r"(b0), "r"(b1));
}

__device__ __forceinline__ void mma16816h(float* d, const uint32_t* a,
                                          uint32_t b0, uint32_t b1) {
    asm volatile(
        "mma.sync.aligned.m16n8k16.row.col.f32.f16.f16.f32 "
        "{%0,%1,%2,%3}, {%4,%5,%6,%7}, {%8,%9}, {%0,%1,%2,%3};"
        : "+f"(d[0]), "+f"(d[1]), "+f"(d[2]), "+f"(d[3])
        : "r"(a[0]), "r"(a[1]), "r"(a[2]), "r"(a[3]), "r"(b0), "r"(b1));
}

__device__ __forceinline__ void ldsm4(uint32_t* r, uint32_t addr) {
    asm volatile("ldmatrix.sync.aligned.m8n8.x4.shared.b16 {%0,%1,%2,%3}, [%4];"
                 : "=r"(r[0]), "=r"(r[1]), "=r"(r[2]), "=r"(r[3]) : "r"(addr));
}
__device__ __forceinline__ void ldsm4t(uint32_t* r, uint32_t addr) {
    asm volatile("ldmatrix.sync.aligned.m8n8.x4.trans.shared.b16 {%0,%1,%2,%3}, [%4];"
                 : "=r"(r[0]), "=r"(r[1]), "=r"(r[2]), "=r"(r[3]) : "r"(addr));
}

__device__ __forceinline__ uint32_t pack2bf(float a, float b) {
    __nv_bfloat162 t = __floats2bfloat162_rn(a, b);
    return *(uint32_t*)&t;
}
__device__ __forceinline__ uint32_t pack2h(float a, float b) {
    __half2 t = __floats2half2_rn(a, b);
    return *(uint32_t*)&t;
}

// ================= scratch (device globals) =================
__device__ float g_Qp[S_LEN * (HQ * HD)];
__device__ float g_Kp[S_LEN * (HKV * HD)];
__device__ float g_Vp[S_LEN * (HKV * HD)];

__device__ __nv_bfloat16 g_hid_h[S_LEN * H_DIM];
__device__ __nv_bfloat16 g_hid_l[S_LEN * H_DIM];
__device__ __half        g_hid_fh[S_LEN * H_DIM];
__device__ __half        g_hid_fl[S_LEN * H_DIM];
__device__ __nv_bfloat16 g_wq_h[HQ * HD * H_DIM];
__device__ __nv_bfloat16 g_wq_l[HQ * HD * H_DIM];
__device__ __nv_bfloat16 g_wk_h[HKV * HD * H_DIM];
__device__ __nv_bfloat16 g_wk_l[HKV * HD * H_DIM];
__device__ __half        g_wv_f[HKV * HD * H_DIM];
__device__ __half        g_wo_f[H_DIM * HQ * HD];
__device__ __half        g_ao_fh[S_LEN * HQ * HD];
__device__ __half        g_ao_fl[S_LEN * HQ * HD];

__device__ __nv_bfloat16 g_qr_h[HQ * S_LEN * HD];
__device__ __nv_bfloat16 g_qr_l[HQ * S_LEN * HD];
__device__ __nv_bfloat16 g_kr_h[HKV * S_LEN * HD];
__device__ __nv_bfloat16 g_kr_l[HKV * S_LEN * HD];
__device__ __nv_bfloat16 g_vr_h[HKV * S_LEN * HD];
__device__ __nv_bfloat16 g_vr_l[HKV * S_LEN * HD];

// ====== fused cvt: hid -> bf16 h/l + fp16 h/l; Wq,Wk -> bf16 h/l; Wv,Wo -> fp16
#define N4_HID (S_LEN * H_DIM / 4)
#define N4_WQ  (HQ * HD * H_DIM / 4)
#define N4_WK  (HKV * HD * H_DIM / 4)
#define N4_WV  (HKV * HD * H_DIM / 4)
#define N4_WO  (H_DIM * HQ * HD / 4)
#define N4_TOT (N4_HID + N4_WQ + N4_WK + N4_WV + N4_WO)

__device__ __forceinline__ void bf_split4(float4 v, __nv_bfloat16* hi,
                                          __nv_bfloat16* lo, size_t j) {
    union { ushort4 u; __nv_bfloat16 b[4]; } H, L;
    H.b[0] = __float2bfloat16(v.x);
    H.b[1] = __float2bfloat16(v.y);
    H.b[2] = __float2bfloat16(v.z);
    H.b[3] = __float2bfloat16(v.w);
    L.b[0] = __float2bfloat16(v.x - __bfloat162float(H.b[0]));
    L.b[1] = __float2bfloat16(v.y - __bfloat162float(H.b[1]));
    L.b[2] = __float2bfloat16(v.z - __bfloat162float(H.b[2]));
    L.b[3] = __float2bfloat16(v.w - __bfloat162float(H.b[3]));
    *(ushort4*)(hi + 4 * j) = H.u;
    *(ushort4*)(lo + 4 * j) = L.u;
}

__device__ __forceinline__ void h_split4(float4 v, __half* hi, __half* lo, size_t j) {
    union { ushort4 u; __half b[4]; } H, L;
    H.b[0] = __float2half_rn(v.x);
    H.b[1] = __float2half_rn(v.y);
    H.b[2] = __float2half_rn(v.z);
    H.b[3] = __float2half_rn(v.w);
    L.b[0] = __float2half_rn(v.x - __half2float(H.b[0]));
    L.b[1] = __float2half_rn(v.y - __half2float(H.b[1]));
    L.b[2] = __float2half_rn(v.z - __half2float(H.b[2]));
    L.b[3] = __float2half_rn(v.w - __half2float(H.b[3]));
    *(ushort4*)(hi + 4 * j) = H.u;
    *(ushort4*)(lo + 4 * j) = L.u;
}

__global__ __launch_bounds__(256)
void cvt_all(const float4* __restrict__ hid, const float4* __restrict__ wq,
             const float4* __restrict__ wk, const float4* __restrict__ wv,
             const float4* __restrict__ wo,
             __nv_bfloat16* __restrict__ hidh, __nv_bfloat16* __restrict__ hidl,
             __half* __restrict__ hidfh, __half* __restrict__ hidfl,
             __nv_bfloat16* __restrict__ wqh,  __nv_bfloat16* __restrict__ wql,
             __nv_bfloat16* __restrict__ wkh,  __nv_bfloat16* __restrict__ wkl,
             __half* __restrict__ wvf, __half* __restrict__ wof) {
    int i = blockIdx.x * blockDim.x + threadIdx.x;
    if (i >= N4_TOT) return;
    int j = i;
    if (j < N4_HID) {
        float4 v = hid[j];
        bf_split4(v, hidh, hidl, (size_t)j);
        h_split4(v, hidfh, hidfl, (size_t)j);
    } else if ((j -= N4_HID) < N4_WQ) {
        bf_split4(wq[j], wqh, wql, (size_t)j);
    } else if ((j -= N4_WQ) < N4_WK) {
        bf_split4(wk[j], wkh, wkl, (size_t)j);
    } else if ((j -= N4_WK) < N4_WV) {
        float4 v = wv[j];
        union { ushort4 u; __half b[4]; } H;
        H.b[0] = __float2half_rn(v.x); H.b[1] = __float2half_rn(v.y);
        H.b[2] = __float2half_rn(v.z); H.b[3] = __float2half_rn(v.w);
        *(ushort4*)(wvf + 4 * (size_t)j) = H.u;
    } else {
        j -= N4_WV;
        float4 v = wo[j];
        union { ushort4 u; __half b[4]; } H;
        H.b[0] = __float2half_rn(v.x); H.b[1] = __float2half_rn(v.y);
        H.b[2] = __float2half_rn(v.z); H.b[3] = __float2half_rn(v.w);
        *(ushort4*)(wof + 4 * (size_t)j) = H.u;
    }
}

// swizzle for 64B-pitch stages
__device__ __forceinline__ uint32_t gsw(int r, int c) {   // c = 16B chunk 0..3
    return (uint32_t)(r * 64 + ((c ^ (r & 3)) * 16));
}

// ================= bf16 3-term GEMM (Q/K projections) ======================
// CTA 64x128, 128 threads, warp tile 32x64, BK=32, 3-stage ring, 3 CTA/SM.
#define G_MATA 4096
#define G_MATB 8192
#define G_A_H 0
#define G_A_L 4096
#define G_B_H 8192
#define G_B_L 16384
#define G_SS  24576
#define SMEM_GEMM (3 * G_SS)

__global__ __launch_bounds__(128, 3)
void gemm_bf16x3(const __nv_bfloat16* __restrict__ Ah, const __nv_bfloat16* __restrict__ Al,
                 const __nv_bfloat16* __restrict__ Bh, const __nv_bfloat16* __restrict__ Bl,
                 float* __restrict__ C, int N, int K) {
    extern __shared__ char smemc[];
    const uint32_t sb = smem_u32(smemc);
    const int tid = threadIdx.x;
    const int lane = tid & 31;
    const int w = tid >> 5;
    const int wm = (w >> 1) * 32;
    const int wn = (w & 1) * 64;
    const int bm = blockIdx.y * 64;
    const int bn = blockIdx.x * 128;
    const int nkb = K / 32;

    auto load_stage = [&](int s, int kblk) {
        const uint32_t st = sb + s * G_SS;
#pragma unroll
        for (int m = 0; m < 2; m++) {
            const __nv_bfloat16* src = (m ? Al : Ah) + (size_t)bm * K + kblk;
            const uint32_t dstb = st + G_A_H + m * G_MATA;
#pragma unroll
            for (int i = 0; i < 2; i++) {
                int flat = tid + i * 128;
                int r = flat >> 2, c = flat & 3;
                CP_ASYNC16(dstb + gsw(r, c), src + (size_t)r * K + c * 8);
            }
        }
#pragma unroll
        for (int m = 0; m < 2; m++) {
            const __nv_bfloat16* src = (m ? Bl : Bh) + (size_t)bn * K + kblk;
            const uint32_t dstb = st + G_B_H + m * G_MATB;
#pragma unroll
            for (int i = 0; i < 4; i++) {
                int flat = tid + i * 128;
                int r = flat >> 2, c = flat & 3;
                CP_ASYNC16(dstb + gsw(r, c), src + (size_t)r * K + c * 8);
            }
        }
    };

    float acc[2][8][4];
#pragma unroll
    for (int i = 0; i < 2; i++)
#pragma unroll
        for (int j = 0; j < 8; j++)
#pragma unroll
            for (int q = 0; q < 4; q++) acc[i][j][q] = 0.f;

    load_stage(0, 0);  CP_COMMIT();
    load_stage(1, 32); CP_COMMIT();
    load_stage(2, 64); CP_COMMIT();

    const int aro = (lane & 7) + 8 * ((lane >> 3) & 1);
    const int acs = (lane >> 4);
    const int bro = (lane & 7) + 8 * ((lane >> 4) & 1);
    const int bcs = ((lane >> 3) & 1);

    int s = 0;
    for (int kb = 0; kb < nkb; kb++) {
        CP_WAIT1();
        __syncthreads();
        if (kb >= 1 && kb + 2 < nkb) load_stage((kb + 2) % 3, (kb + 2) * 32);
        if (kb >= 1) CP_COMMIT();
        const uint32_t st = sb + s * G_SS;

#pragma unroll
        for (int kk = 0; kk < 2; kk++) {
            uint32_t ah[2][4], al[2][4];
#pragma unroll
            for (int i = 0; i < 2; i++) {
                int r = wm + i * 16 + aro;
                uint32_t ab = st + G_A_H + gsw(r, kk * 2 + acs);
                ldsm4(ah[i], ab);
                ldsm4(al[i], ab + G_MATA);
            }
#pragma unroll
            for (int jp = 0; jp < 4; jp++) {
                uint32_t bh[4], bl[4];
                int r = wn + jp * 16 + bro;
                uint32_t bb = st + G_B_H + gsw(r, kk * 2 + bcs);
                ldsm4(bh, bb);
                ldsm4(bl, bb + G_MATB);
#pragma unroll
                for (int i = 0; i < 2; i++) {
                    mma16816(acc[i][2 * jp],     ah[i], bh[0], bh[1]);
                    mma16816(acc[i][2 * jp + 1], ah[i], bh[2], bh[3]);
                }
#pragma unroll
                for (int i = 0; i < 2; i++) {
                    mma16816(acc[i][2 * jp],     ah[i], bl[0], bl[1]);
                    mma16816(acc[i][2 * jp + 1], ah[i], bl[2], bl[3]);
                }
#pragma unroll
                for (int i = 0; i < 2; i++) {
                    mma16816(acc[i][2 * jp],     al[i], bh[0], bh[1]);
                    mma16816(acc[i][2 * jp + 1], al[i], bh[2], bh[3]);
                }
            }
        }
        s = (s == 2) ? 0 : s + 1;
    }

    const int lr = lane >> 2;
    const int lc = lane & 3;
#pragma unroll
    for (int i = 0; i < 2; i++) {
        const int r0 = bm + wm + i * 16 + lr;
#pragma unroll
        for (int j = 0; j < 8; j++) {
            const int c0 = bn + wn + j * 8 + lc * 2;
            *(float2*)(C + (size_t)r0 * N + c0) = make_float2(acc[i][j][0], acc[i][j][1]);
            *(float2*)(C + (size_t)(r0 + 8) * N + c0) = make_float2(acc[i][j][2], acc[i][j][3]);
        }
    }
}

// ============ fp16 2-term GEMM (V / output projections) ====================
// A split fp16 hi/lo (exact), B single fp16 (error ~2^-11.8, un-amplified path).
#define F_A_H 0
#define F_A_L 4096
#define F_B   8192
#define F_SS  16384
#define SMEM_GEMM_F (3 * F_SS)

__global__ __launch_bounds__(128, 3)
void gemm_fp16x2(const __half* __restrict__ Ah, const __half* __restrict__ Al,
                 const __half* __restrict__ B,
                 float* __restrict__ C, int N, int K) {
    extern __shared__ char smemc[];
    const uint32_t sb = smem_u32(smemc);
    const int tid = threadIdx.x;
    const int lane = tid & 31;
    const int w = tid >> 5;
    const int wm = (w >> 1) * 32;
    const int wn = (w & 1) * 64;
    const int bm = blockIdx.y * 64;
    const int bn = blockIdx.x * 128;
    const int nkb = K / 32;

    auto load_stage = [&](int s, int kblk) {
        const uint32_t st = sb + s * F_SS;
#pragma unroll
        for (int m = 0; m < 2; m++) {
            const __half* src = (m ? Al : Ah) + (size_t)bm * K + kblk;
            const uint32_t dstb = st + F_A_H + m * 4096;
#pragma unroll
            for (int i = 0; i < 2; i++) {
                int flat = tid + i * 128;
                int r = flat >> 2, c = flat & 3;
                CP_ASYNC16(dstb + gsw(r, c), src + (size_t)r * K + c * 8);
            }
        }
        {
            const __half* src = B + (size_t)bn * K + kblk;
            const uint32_t dstb = st + F_B;
#pragma unroll
            for (int i = 0; i < 4; i++) {
                int flat = tid + i * 128;
                int r = flat >> 2, c = flat & 3;
                CP_ASYNC16(dstb + gsw(r, c), src + (size_t)r * K + c * 8);
            }
        }
    };

    float acc[2][8][4];
#pragma unroll
    for (int i = 0; i < 2; i++)
#pragma unroll
        for (int j = 0; j < 8; j++)
#pragma unroll
            for (int q = 0; q < 4; q++) acc[i][j][q] = 0.f;

    load_stage(0, 0);  CP_COMMIT();
    load_stage(1, 32); CP_COMMIT();
    load_stage(2, 64); CP_COMMIT();

    const int aro = (lane & 7) + 8 * ((lane >> 3) & 1);
    const int acs = (lane >> 4);
    const int bro = (lane & 7) + 8 * ((lane >> 4) & 1);
    const int bcs = ((lane >> 3) & 1);

    int s = 0;
    for (int kb = 0; kb < nkb; kb++) {
        CP_WAIT1();
        __syncthreads();
        if (kb >= 1 && kb + 2 < nkb) load_stage((kb + 2) % 3, (kb + 2) * 32);
        if (kb >= 1) CP_COMMIT();
        const uint32_t st = sb + s * F_SS;

#pragma unroll
        for (int kk = 0; kk < 2; kk++) {
            uint32_t ah[2][4], al[2][4];
#pragma unroll
            for (int i = 0; i < 2; i++) {
                int r = wm + i * 16 + aro;
                uint32_t ab = st + F_A_H + gsw(r, kk * 2 + acs);
                ldsm4(ah[i], ab);
                ldsm4(al[i], ab + 4096);
            }
#pragma unroll
            for (int jp = 0; jp < 4; jp++) {
                uint32_t bh[4];
                int r = wn + jp * 16 + bro;
                ldsm4(bh, st + F_B + gsw(r, kk * 2 + bcs));
#pragma unroll
                for (int i = 0; i < 2; i++) {
                    mma16816h(acc[i][2 * jp],     ah[i], bh[0], bh[1]);
                    mma16816h(acc[i][2 * jp + 1], ah[i], bh[2], bh[3]);
                }
#pragma unroll
                for (int i = 0; i < 2; i++) {
                    mma16816h(acc[i][2 * jp],     al[i], bh[0], bh[1]);
                    mma16816h(acc[i][2 * jp + 1], al[i], bh[2], bh[3]);
                }
            }
        }
        s = (s == 2) ? 0 : s + 1;
    }

    const int lr = lane >> 2;
    const int lc = lane & 3;
#pragma unroll
    for (int i = 0; i < 2; i++) {
        const int r0 = bm + wm + i * 16 + lr;
#pragma unroll
        for (int j = 0; j < 8; j++) {
            const int c0 = bn + wn + j * 8 + lc * 2;
            *(float2*)(C + (size_t)r0 * N + c0) = make_float2(acc[i][j][0], acc[i][j][1]);
            *(float2*)(C + (size_t)(r0 + 8) * N + c0) = make_float2(acc[i][j][2], acc[i][j][3]);
        }
    }
}

// ======= RMSNorm + RoPE -> bf16 hi/lo head-major (1 block per position) =====
__global__ __launch_bounds__(256)
void norm_rope2(const float* __restrict__ Qp, const float* __restrict__ Kp,
                const float* __restrict__ Vp,
                const float* __restrict__ cosb, const float* __restrict__ sinb,
                const float* __restrict__ qw, const float* __restrict__ kw,
                __nv_bfloat16* __restrict__ Qrh, __nv_bfloat16* __restrict__ Qrl,
                __nv_bfloat16* __restrict__ Krh, __nv_bfloat16* __restrict__ Krl,
                __nv_bfloat16* __restrict__ Vrh, __nv_bfloat16* __restrict__ Vrl) {
    const int s = blockIdx.x;
    const int d = threadIdx.x;

    __shared__ float cs[HD], sn[HD], qws[HD], kws[HD], red[8], ysh[HD];
    cs[d]  = cosb[(size_t)s * HD + d];
    sn[d]  = sinb[(size_t)s * HD + d];
    qws[d] = qw[d];
    kws[d] = kw[d];
    __syncthreads();

    for (int hh = 0; hh < HQ + 2 * HKV; hh++) {
        const float* src;
        __nv_bfloat16 *dsth, *dstl;
        const float* wv = nullptr;
        bool do_rope = false;

        if (hh < HQ) {
            src = Qp + (size_t)s * (HQ * HD) + hh * HD;
            dsth = Qrh + ((size_t)hh * S_LEN + s) * HD;
            dstl = Qrl + ((size_t)hh * S_LEN + s) * HD;
            wv = qws; do_rope = true;
        } else if (hh < HQ + HKV) {
            int h = hh - HQ;
            src = Kp + (size_t)s * (HKV * HD) + h * HD;
            dsth = Krh + ((size_t)h * S_LEN + s) * HD;
            dstl = Krl + ((size_t)h * S_LEN + s) * HD;
            wv = kws; do_rope = true;
        } else {
            int h = hh - HQ - HKV;
            src = Vp + (size_t)s * (HKV * HD) + h * HD;
            dsth = Vrh + ((size_t)h * S_LEN + s) * HD;
            dstl = Vrl + ((size_t)h * S_LEN + s) * HD;
        }

        float x = src[d];
        float v = x * x;
#pragma unroll
        for (int off = 16; off > 0; off >>= 1)
            v += __shfl_xor_sync(0xffffffffu, v, off);
        if ((d & 31) == 0) red[d >> 5] = v;
        __syncthreads();
        float tot = 0.f;
#pragma unroll
        for (int r = 0; r < 8; r++) tot += red[r];

        float rms = rsqrtf(tot * (1.0f / HD) + 1e-6f);
        float y = x * rms;
        if (wv) y *= wv[d];

        if (do_rope) {
            ysh[d] = y;
            __syncthreads();
            float rot = (d < HD / 2) ? -ysh[d + HD / 2] : ysh[d - HD / 2];
            y = y * cs[d] + rot * sn[d];
        }
        __nv_bfloat16 hb = __float2bfloat16(y);
        dsth[d] = hb;
        dstl[d] = __float2bfloat16(y - __bfloat162float(hb));
        __syncthreads();
    }
}

// ================= HMMA flash attention (sliding window + softcap) =========
#define APITCH 528
#define AQH_OFF 0
#define AQL_OFF 33792
#define AKH_OFF 67584
#define AKL_OFF 101376
#define AVH_OFF 135168
#define AVL_OFF 168960
#define APH_OFF 202752
#define APL_OFF 211968
#define ASTAT_OFF 221184
#define SMEM_ATTN 222976

__global__ __launch_bounds__(256, 1)
void attn_mma(const __nv_bfloat16* __restrict__ Qh, const __nv_bfloat16* __restrict__ Ql,
              const __nv_bfloat16* __restrict__ Kh, const __nv_bfloat16* __restrict__ Kl,
              const __nv_bfloat16* __restrict__ Vh, const __nv_bfloat16* __restrict__ Vl,
              __half* __restrict__ AOh, __half* __restrict__ AOl) {
    extern __shared__ char smemc[];
    const uint32_t sb = smem_u32(smemc);
    const int tid = threadIdx.x;
    const int lane = tid & 31;
    const int w = tid >> 5;
    const int h = blockIdx.y;
    const int q0 = blockIdx.x * 64;

    const __nv_bfloat16* qhp = Qh + ((size_t)h * S_LEN + q0) * HD;
    const __nv_bfloat16* qlp = Ql + ((size_t)h * S_LEN + q0) * HD;
    const __nv_bfloat16* khp = Kh + (size_t)(h >> 1) * S_LEN * HD;
    const __nv_bfloat16* klp = Kl + (size_t)(h >> 1) * S_LEN * HD;
    const __nv_bfloat16* vhp = Vh + (size_t)(h >> 1) * S_LEN * HD;
    const __nv_bfloat16* vlp = Vl + (size_t)(h >> 1) * S_LEN * HD;

    float* marr  = (float*)(smemc + ASTAT_OFF);
    float* larr  = marr + 64;
    float* alpha = marr + 128;
    float* pm0   = marr + 192;
    float* pm1   = marr + 256;
    float* ps0   = marr + 320;
    float* ps1   = marr + 384;

    if (tid < 64) { marr[tid] = -1e30f; larr[tid] = 0.f; }

    auto cpQ = [&](uint32_t off, const __nv_bfloat16* src) {
#pragma unroll
        for (int i = 0; i < 8; i++) {
            int flat = tid + i * 256;
            int r = flat >> 5, c = flat & 31;
            CP_ASYNC16(sb + off + r * APITCH + c * 16, src + (size_t)r * HD + c * 8);
        }
    };
    auto cpT = [&](uint32_t off, const __nv_bfloat16* base, int kt) {
#pragma unroll
        for (int i = 0; i < 8; i++) {
            int flat = tid + i * 256;
            int r = flat >> 5, c = flat & 31;
            CP_ASYNC16(sb + off + r * APITCH + c * 16, base + (size_t)(kt + r) * HD + c * 8);
        }
    };

    int klo = q0 - (WIN - 1);
    if (klo < 0) klo = 0;
    const int kt0 = klo & ~63;

    cpQ(AQH_OFF, qhp); cpQ(AQL_OFF, qlp);
    cpT(AKH_OFF, khp, kt0); cpT(AKL_OFF, klp, kt0);
    CP_COMMIT();

    float oacc[16][4];
#pragma unroll
    for (int i = 0; i < 16; i++)
#pragma unroll
        for (int q = 0; q < 4; q++) oacc[i][q] = 0.f;

    const int aro = (lane & 7) + 8 * ((lane >> 3) & 1);
    const int aco = (lane >> 4) * 16;
    const int bro = (lane & 7) + 8 * ((lane >> 4) & 1);
    const int bco = ((lane >> 3) & 1) * 16;
    const int R  = 16 * (w >> 1);
    const int Ch = 32 * (w & 1);
    const int Rp = 16 * (w & 3);
    const int Dq = 128 * (w >> 2);
    const int rl = lane >> 2;

    __syncthreads();

    for (int kt = kt0; kt <= q0; kt += 64) {
        cpT(AVH_OFF, vhp, kt); cpT(AVL_OFF, vlp, kt);
        CP_COMMIT();
        CP_WAIT1();
        __syncthreads();

        // ---------------- QK ----------------
        float sacc[4][4];
#pragma unroll
        for (int i = 0; i < 4; i++)
#pragma unroll
            for (int q = 0; q < 4; q++) sacc[i][q] = 0.f;

#pragma unroll
        for (int ks = 0; ks < 16; ks++) {
            uint32_t aH[4], aL[4];
            uint32_t ab = sb + AQH_OFF + (R + aro) * APITCH + ks * 32 + aco;
            ldsm4(aH, ab);
            ldsm4(aL, ab + (AQL_OFF - AQH_OFF));
            uint32_t bH0[4], bL0[4], bH1[4], bL1[4];
            uint32_t bb0 = sb + AKH_OFF + (Ch + bro) * APITCH + ks * 32 + bco;
            uint32_t bb1 = sb + AKH_OFF + (Ch + 16 + bro) * APITCH + ks * 32 + bco;
            ldsm4(bH0, bb0);
            ldsm4(bL0, bb0 + (AKL_OFF - AKH_OFF));
            ldsm4(bH1, bb1);
            ldsm4(bL1, bb1 + (AKL_OFF - AKH_OFF));
            mma16816(sacc[0], aH, bH0[0], bH0[1]);
            mma16816(sacc[1], aH, bH0[2], bH0[3]);
            mma16816(sacc[2], aH, bH1[0], bH1[1]);
            mma16816(sacc[3], aH, bH1[2], bH1[3]);
            mma16816(sacc[0], aH, bL0[0], bL0[1]);
            mma16816(sacc[1], aH, bL0[2], bL0[3]);
            mma16816(sacc[2], aH, bL1[0], bL1[1]);
            mma16816(sacc[3], aH, bL1[2], bL1[3]);
            mma16816(sacc[0], aL, bH0[0], bH0[1]);
            mma16816(sacc[1], aL, bH0[2], bH0[3]);
            mma16816(sacc[2], aL, bH1[0], bH1[1]);
            mma16816(sacc[3], aL, bH1[2], bH1[3]);
        }

        const int rlo = R + rl, rhi = R + rl + 8;
        float mx0 = -1e30f, mx1 = -1e30f;
#pragma unroll
        for (int n8 = 0; n8 < 4; n8++) {
#pragma unroll
            for (int e = 0; e < 4; e++) {
                int row = (e < 2) ? rlo : rhi;
                int kg = kt + Ch + n8 * 8 + (lane & 3) * 2 + (e & 1);
                int qg = q0 + row;
                float s = 50.0f * tanhf(sacc[n8][e] * 0.02f);
                bool ok = (kg <= qg) && (qg - kg < WIN);
                s = ok ? s : -1e30f;
                sacc[n8][e] = s;
                if (e < 2) mx0 = fmaxf(mx0, s); else mx1 = fmaxf(mx1, s);
            }
        }
        mx0 = fmaxf(mx0, __shfl_xor_sync(0xffffffffu, mx0, 1));
        mx0 = fmaxf(mx0, __shfl_xor_sync(0xffffffffu, mx0, 2));
        mx1 = fmaxf(mx1, __shfl_xor_sync(0xffffffffu, mx1, 1));
        mx1 = fmaxf(mx1, __shfl_xor_sync(0xffffffffu, mx1, 2));
        if ((lane & 3) == 0) {
            float* pmh = (w & 1) ? pm1 : pm0;
            pmh[rlo] = mx0; pmh[rhi] = mx1;
        }
        __syncthreads();

        if (kt + 64 <= q0) { cpT(AKH_OFF, khp, kt + 64); cpT(AKL_OFF, klp, kt + 64); }
        CP_COMMIT();

        if (tid < 64) {
            float mo = marr[tid];
            float mn = fmaxf(mo, fmaxf(pm0[tid], pm1[tid]));
            alpha[tid] = (mn > -1e29f) ? __expf(mo - mn) : 1.f;
            marr[tid] = mn;
        }
        __syncthreads();

        {
            float mn0 = marr[rlo], mn1 = marr[rhi];
            float sum0 = 0.f, sum1 = 0.f;
#pragma unroll
            for (int n8 = 0; n8 < 4; n8++) {
                float p0 = (sacc[n8][0] > -1e29f) ? __expf(sacc[n8][0] - mn0) : 0.f;
                float p1 = (sacc[n8][1] > -1e29f) ? __expf(sacc[n8][1] - mn0) : 0.f;
                float p2 = (sacc[n8][2] > -1e29f) ? __expf(sacc[n8][2] - mn1) : 0.f;
                float p3 = (sacc[n8][3] > -1e29f) ? __expf(sacc[n8][3] - mn1) : 0.f;
                sum0 += p0 + p1; sum1 += p2 + p3;
                int cb = (Ch + n8 * 8 + (lane & 3) * 2) * 2;
                uint32_t hlo = pack2bf(p0, p1);
                uint32_t hhi = pack2bf(p2, p3);
                float r0a = __bfloat162float(__nv_bfloat16(((__nv_bfloat162*)&hlo)->x));
                float r0b = __bfloat162float(__nv_bfloat16(((__nv_bfloat162*)&hlo)->y));
                float r1a = __bfloat162float(__nv_bfloat16(((__nv_bfloat162*)&hhi)->x));
                float r1b = __bfloat162float(__nv_bfloat16(((__nv_bfloat162*)&hhi)->y));
                *(uint32_t*)(smemc + APH_OFF + rlo * 144 + cb) = hlo;
                *(uint32_t*)(smemc + APH_OFF + rhi * 144 + cb) = hhi;
                *(uint32_t*)(smemc + APL_OFF + rlo * 144 + cb) = pack2bf(p0 - r0a, p1 - r0b);
                *(uint32_t*)(smemc + APL_OFF + rhi * 144 + cb) = pack2bf(p2 - r1a, p3 - r1b);
            }
            sum0 += __shfl_xor_sync(0xffffffffu, sum0, 1);
            sum0 += __shfl_xor_sync(0xffffffffu, sum0, 2);
            sum1 += __shfl_xor_sync(0xffffffffu, sum1, 1);
            sum1 += __shfl_xor_sync(0xffffffffu, sum1, 2);
            if ((lane & 3) == 0) {
                float* psh = (w & 1) ? ps1 : ps0;
                psh[rlo] = sum0; psh[rhi] = sum1;
            }
        }
        __syncthreads();
        if (tid < 64) larr[tid] = alpha[tid] * larr[tid] + ps0[tid] + ps1[tid];
        CP_WAIT1();
        __syncthreads();

        // ---------------- PV ----------------
        {
            float a0 = alpha[Rp + rl], a1 = alpha[Rp + 8 + rl];
#pragma unroll
            for (int n8 = 0; n8 < 16; n8++) {
                oacc[n8][0] *= a0; oacc[n8][1] *= a0;
                oacc[n8][2] *= a1; oacc[n8][3] *= a1;
            }
            const int vco = ((lane >> 4) & 1) * 8;
            const int vrw = (lane & 7) + 8 * ((lane >> 3) & 1);
#pragma unroll
            for (int ks = 0; ks < 4; ks++) {
                uint32_t pH[4], pL[4];
                uint32_t pb = sb + APH_OFF + (Rp + aro) * 144 + ks * 32 + aco;
                ldsm4(pH, pb);
                ldsm4(pL, pb + (APL_OFF - APH_OFF));
#pragma unroll
                for (int dt = 0; dt < 8; dt += 2) {
                    uint32_t vH0[4], vL0[4], vH1[4], vL1[4];
                    uint32_t vb0 = sb + AVH_OFF + (ks * 16 + vrw) * APITCH +
                                   (Dq + dt * 16 + vco) * 2;
                    uint32_t vb1 = vb0 + 32;
                    ldsm4t(vH0, vb0);
                    ldsm4t(vL0, vb0 + (AVL_OFF - AVH_OFF));
                    ldsm4t(vH1, vb1);
                    ldsm4t(vL1, vb1 + (AVL_OFF - AVH_OFF));
                    mma16816(oacc[2 * dt],     pH, vH0[0], vH0[1]);
                    mma16816(oacc[2 * dt + 1], pH, vH0[2], vH0[3]);
                    mma16816(oacc[2 * dt + 2], pH, vH1[0], vH1[1]);
                    mma16816(oacc[2 * dt + 3], pH, vH1[2], vH1[3]);
                    mma16816(oacc[2 * dt],     pH, vL0[0], vL0[1]);
                    mma16816(oacc[2 * dt + 1], pH, vL0[2], vL0[3]);
                    mma16816(oacc[2 * dt + 2], pH, vL1[0], vL1[1]);
                    mma16816(oacc[2 * dt + 3], pH, vL1[2], vL1[3]);
                    mma16816(oacc[2 * dt],     pL, vH0[0], vH0[1]);
                    mma16816(oacc[2 * dt + 1], pL, vH0[2], vH0[3]);
                    mma16816(oacc[2 * dt + 2], pL, vH1[0], vH1[1]);
                    mma16816(oacc[2 * dt + 3], pL, vH1[2], vH1[3]);
                }
            }
        }
        __syncthreads();
    }

    // output: fp16 hi/lo, [S][HQ*HD]
    {
        float inv0 = 1.0f / larr[Rp + rl];
        float inv1 = 1.0f / larr[Rp + 8 + rl];
        const int r0 = q0 + Rp + rl;
#pragma unroll
        for (int n8 = 0; n8 < 16; n8++) {
            int col = h * HD + Dq + n8 * 8 + (lane & 3) * 2;
            float o0 = oacc[n8][0] * inv0, o1 = oacc[n8][1] * inv0;
            float o2 = oacc[n8][2] * inv1, o3 = oacc[n8][3] * inv1;
            uint32_t h0 = pack2h(o0, o1);
            __half2 hv0 = *(__half2*)&h0;
            uint32_t l0 = pack2h(o0 - __half2float(hv0.x), o1 - __half2float(hv0.y));
            uint32_t h1 = pack2h(o2, o3);
            __half2 hv1 = *(__half2*)&h1;
            uint32_t l1 = pack2h(o2 - __half2float(hv1.x), o3 - __half2float(hv1.y));
            *(uint32_t*)(AOh + (size_t)r0 * (HQ * HD) + col) = h0;
            *(uint32_t*)(AOl + (size_t)r0 * (HQ * HD) + col) = l0;
            *(uint32_t*)(AOh + (size_t)(r0 + 8) * (HQ * HD) + col) = h1;
            *(uint32_t*)(AOl + (size_t)(r0 + 8) * (HQ * HD) + col) = l1;
        }
    }
}

// ================= launch =================
extern "C" void kernel_launch(void* const* d_in, const int* in_sizes, int n_in,
                              void* d_out, int out_size) {
    const float* hidden = (const float*)d_in[0];
    const float* cosb   = (const float*)d_in[1];
    const float* sinb   = (const float*)d_in[2];
    // d_in[3] = attention_mask (sliding window, implemented analytically)
    const float* Wq = (const float*)d_in[4];
    const float* Wk = (const float*)d_in[5];
    const float* Wv = (const float*)d_in[6];
    const float* Wo = (const float*)d_in[7];
    const float* qw = (const float*)d_in[8];
    const float* kw = (const float*)d_in[9];
    float* out = (float*)d_out;

    float *Qp, *Kp, *Vp;
    cudaGetSymbolAddress((void**)&Qp, g_Qp);
    cudaGetSymbolAddress((void**)&Kp, g_Kp);
    cudaGetSymbolAddress((void**)&Vp, g_Vp);

    __nv_bfloat16 *hidh, *hidl, *wqh, *wql, *wkh, *wkl;
    __half *hidfh, *hidfl, *wvf, *wof, *aofh, *aofl;
    __nv_bfloat16 *qrh, *qrl, *krh, *krl, *vrh, *vrl;
    cudaGetSymbolAddress((void**)&hidh, g_hid_h);
    cudaGetSymbolAddress((void**)&hidl, g_hid_l);
    cudaGetSymbolAddress((void**)&hidfh, g_hid_fh);
    cudaGetSymbolAddress((void**)&hidfl, g_hid_fl);
    cudaGetSymbolAddress((void**)&wqh, g_wq_h);
    cudaGetSymbolAddress((void**)&wql, g_wq_l);
    cudaGetSymbolAddress((void**)&wkh, g_wk_h);
    cudaGetSymbolAddress((void**)&wkl, g_wk_l);
    cudaGetSymbolAddress((void**)&wvf, g_wv_f);
    cudaGetSymbolAddress((void**)&wof, g_wo_f);
    cudaGetSymbolAddress((void**)&aofh, g_ao_fh);
    cudaGetSymbolAddress((void**)&aofl, g_ao_fl);
    cudaGetSymbolAddress((void**)&qrh, g_qr_h);
    cudaGetSymbolAddress((void**)&qrl, g_qr_l);
    cudaGetSymbolAddress((void**)&krh, g_kr_h);
    cudaGetSymbolAddress((void**)&krl, g_kr_l);
    cudaGetSymbolAddress((void**)&vrh, g_vr_h);
    cudaGetSymbolAddress((void**)&vrl, g_vr_l);

    cudaFuncSetAttribute((const void*)gemm_bf16x3,
                         cudaFuncAttributeMaxDynamicSharedMemorySize, SMEM_GEMM);
    cudaFuncSetAttribute((const void*)gemm_fp16x2,
                         cudaFuncAttributeMaxDynamicSharedMemorySize, SMEM_GEMM_F);
    cudaFuncSetAttribute((const void*)attn_mma,
                         cudaFuncAttributeMaxDynamicSharedMemorySize, SMEM_ATTN);

    // fused conversions (one launch)
    cvt_all<<<(N4_TOT + 255) / 256, 256>>>(
        (const float4*)hidden, (const float4*)Wq, (const float4*)Wk,
        (const float4*)Wv, (const float4*)Wo,
        hidh, hidl, hidfh, hidfl, wqh, wql, wkh, wkl, wvf, wof);

    // Q/K projections: bf16 3-term (precision-critical path)
    gemm_bf16x3<<<dim3(16, 64), 128, SMEM_GEMM>>>(hidh, hidl, wqh, wql, Qp, HQ * HD, H_DIM);
    gemm_bf16x3<<<dim3(8, 64), 128, SMEM_GEMM>>>(hidh, hidl, wkh, wkl, Kp, HKV * HD, H_DIM);
    // V projection: fp16 2-term (error un-amplified)
    gemm_fp16x2<<<dim3(8, 64), 128, SMEM_GEMM_F>>>(hidfh, hidfl, wvf, Vp, HKV * HD, H_DIM);

    // RMSNorm + RoPE -> bf16 hi/lo head-major
    norm_rope2<<<S_LEN, 256>>>(Qp, Kp, Vp, cosb, sinb, qw, kw,
                               qrh, qrl, krh, krl, vrh, vrl);

    // tensor-core flash attention -> fp16 hi/lo AO
    attn_mma<<<dim3(S_LEN / 64, HQ), 256, SMEM_ATTN>>>(qrh, qrl, krh, krl, vrh, vrl, aofh, aofl);

    // output projection: fp16 2-term
    gemm_fp16x2<<<dim3(16, 64), 128, SMEM_GEMM_F>>>(aofh, aofl, wof, out, H_DIM, H_DIM);
}

// round 13
// speedup vs baseline: 1.2720x; 1.1046x over previous
#include <cuda_runtime.h>
#include <cuda_bf16.h>
#include <cuda_fp16.h>
#include <math.h>
#include <stdint.h>

#define S_LEN 4096
#define H_DIM 2048
#define HQ 8
#define HKV 4
#define HD 256
#define WIN 1024
#define NQK (HQ * HD + HKV * HD)   // 3072 combined Q+K output width

// ================= portable PTX helpers (baseline ISA only) =================
__device__ __forceinline__ uint32_t smem_u32(const void* p) {
    uint32_t a;
    asm("{ .reg .u64 t; cvta.to.shared.u64 t, %1; cvt.u32.u64 %0, t; }"
        : "=r"(a) : "l"(p));
    return a;
}

#define CP_ASYNC16(dst_u32, src_ptr) \
    asm volatile("cp.async.cg.shared.global [%0], [%1], 16;" \
                 :: "r"(dst_u32), "l"(src_ptr) : "memory")
#define CP_COMMIT() asm volatile("cp.async.commit_group;" ::: "memory")
#define CP_WAIT1()  asm volatile("cp.async.wait_group 1;" ::: "memory")

__device__ __forceinline__ void mma16816(float* d, const uint32_t* a,
                                         uint32_t b0, uint32_t b1) {
    asm volatile(
        "mma.sync.aligned.m16n8k16.row.col.f32.bf16.bf16.f32 "
        "{%0,%1,%2,%3}, {%4,%5,%6,%7}, {%8,%9}, {%0,%1,%2,%3};"
        : "+f"(d[0]), "+f"(d[1]), "+f"(d[2]), "+f"(d[3])
        : "r"(a[0]), "r"(a[1]), "r"(a[2]), "r"(a[3]), "r"(b0), "r"(b1));
}

__device__ __forceinline__ void mma16816h(float* d, const uint32_t* a,
                                          uint32_t b0, uint32_t b1) {
    asm volatile(
        "mma.sync.aligned.m16n8k16.row.col.f32.f16.f16.f32 "
        "{%0,%1,%2,%3}, {%4,%5,%6,%7}, {%8,%9}, {%0,%1,%2,%3};"
        : "+f"(d[0]), "+f"(d[1]), "+f"(d[2]), "+f"(d[3])
        : "r"(a[0]), "r"(a[1]), "r"(a[2]), "r"(a[3]), "r"(b0), "r"(b1));
}

__device__ __forceinline__ void ldsm4(uint32_t* r, uint32_t addr) {
    asm volatile("ldmatrix.sync.aligned.m8n8.x4.shared.b16 {%0,%1,%2,%3}, [%4];"
                 : "=r"(r[0]), "=r"(r[1]), "=r"(r[2]), "=r"(r[3]) : "r"(addr));
}
__device__ __forceinline__ void ldsm4t(uint32_t* r, uint32_t addr) {
    asm volatile("ldmatrix.sync.aligned.m8n8.x4.trans.shared.b16 {%0,%1,%2,%3}, [%4];"
                 : "=r"(r[0]), "=r"(r[1]), "=r"(r[2]), "=r"(r[3]) : "r"(addr));
}

__device__ __forceinline__ uint32_t pack2bf(float a, float b) {
    __nv_bfloat162 t = __floats2bfloat162_rn(a, b);
    return *(uint32_t*)&t;
}
__device__ __forceinline__ uint32_t pack2h(float a, float b) {
    __half2 t = __floats2half2_rn(a, b);
    return *(uint32_t*)&t;
}

// inf-safe fast softcap: 50*tanh(x/50)
__device__ __forceinline__ float softcap50(float x) {
    float e = __expf(x * 0.04f);
    return 50.f * (1.f - __fdividef(2.f, e + 1.f));
}

// ================= scratch (device globals) =================
__device__ float g_QKp[S_LEN * NQK];         // combined Q|K projection
__device__ float g_Vp[S_LEN * (HKV * HD)];

__device__ __nv_bfloat16 g_hid_h[S_LEN * H_DIM];
__device__ __nv_bfloat16 g_hid_l[S_LEN * H_DIM];
__device__ __half        g_hid_fh[S_LEN * H_DIM];
__device__ __half        g_hid_fl[S_LEN * H_DIM];
__device__ __nv_bfloat16 g_wqk_h[NQK * H_DIM];   // Wq rows then Wk rows
__device__ __nv_bfloat16 g_wqk_l[NQK * H_DIM];
__device__ __half        g_wv_f[HKV * HD * H_DIM];
__device__ __half        g_wo_f[H_DIM * HQ * HD];
__device__ __half        g_ao_fh[S_LEN * HQ * HD];
__device__ __half        g_ao_fl[S_LEN * HQ * HD];

__device__ __nv_bfloat16 g_qr_h[HQ * S_LEN * HD];
__device__ __nv_bfloat16 g_qr_l[HQ * S_LEN * HD];
__device__ __nv_bfloat16 g_kr_h[HKV * S_LEN * HD];
__device__ __nv_bfloat16 g_kr_l[HKV * S_LEN * HD];
__device__ __half        g_vr_f[HKV * S_LEN * HD];

// ====== fused cvt ======
#define N4_HID (S_LEN * H_DIM / 4)
#define N4_WQ  (HQ * HD * H_DIM / 4)
#define N4_WK  (HKV * HD * H_DIM / 4)
#define N4_WV  (HKV * HD * H_DIM / 4)
#define N4_WO  (H_DIM * HQ * HD / 4)
#define N4_TOT (N4_HID + N4_WQ + N4_WK + N4_WV + N4_WO)

__device__ __forceinline__ void bf_split4(float4 v, __nv_bfloat16* hi,
                                          __nv_bfloat16* lo, size_t j) {
    union { ushort4 u; __nv_bfloat16 b[4]; } H, L;
    H.b[0] = __float2bfloat16(v.x);
    H.b[1] = __float2bfloat16(v.y);
    H.b[2] = __float2bfloat16(v.z);
    H.b[3] = __float2bfloat16(v.w);
    L.b[0] = __float2bfloat16(v.x - __bfloat162float(H.b[0]));
    L.b[1] = __float2bfloat16(v.y - __bfloat162float(H.b[1]));
    L.b[2] = __float2bfloat16(v.z - __bfloat162float(H.b[2]));
    L.b[3] = __float2bfloat16(v.w - __bfloat162float(H.b[3]));
    *(ushort4*)(hi + 4 * j) = H.u;
    *(ushort4*)(lo + 4 * j) = L.u;
}

__device__ __forceinline__ void h_split4(float4 v, __half* hi, __half* lo, size_t j) {
    union { ushort4 u; __half b[4]; } H, L;
    H.b[0] = __float2half_rn(v.x);
    H.b[1] = __float2half_rn(v.y);
    H.b[2] = __float2half_rn(v.z);
    H.b[3] = __float2half_rn(v.w);
    L.b[0] = __float2half_rn(v.x - __half2float(H.b[0]));
    L.b[1] = __float2half_rn(v.y - __half2float(H.b[1]));
    L.b[2] = __float2half_rn(v.z - __half2float(H.b[2]));
    L.b[3] = __float2half_rn(v.w - __half2float(H.b[3]));
    *(ushort4*)(hi + 4 * j) = H.u;
    *(ushort4*)(lo + 4 * j) = L.u;
}

__device__ __forceinline__ void h_single4(float4 v, __half* dst, size_t j) {
    union { ushort4 u; __half b[4]; } H;
    H.b[0] = __float2half_rn(v.x); H.b[1] = __float2half_rn(v.y);
    H.b[2] = __float2half_rn(v.z); H.b[3] = __float2half_rn(v.w);
    *(ushort4*)(dst + 4 * j) = H.u;
}

__global__ __launch_bounds__(256)
void cvt_all(const float4* __restrict__ hid, const float4* __restrict__ wq,
             const float4* __restrict__ wk, const float4* __restrict__ wv,
             const float4* __restrict__ wo,
             __nv_bfloat16* __restrict__ hidh, __nv_bfloat16* __restrict__ hidl,
             __half* __restrict__ hidfh, __half* __restrict__ hidfl,
             __nv_bfloat16* __restrict__ wqkh, __nv_bfloat16* __restrict__ wqkl,
             __half* __restrict__ wvf, __half* __restrict__ wof) {
    int i = blockIdx.x * blockDim.x + threadIdx.x;
    if (i >= N4_TOT) return;
    int j = i;
    if (j < N4_HID) {
        float4 v = hid[j];
        bf_split4(v, hidh, hidl, (size_t)j);
        h_split4(v, hidfh, hidfl, (size_t)j);
    } else if ((j -= N4_HID) < N4_WQ) {
        bf_split4(wq[j], wqkh, wqkl, (size_t)j);               // Wq rows first
    } else if ((j -= N4_WQ) < N4_WK) {
        bf_split4(wk[j], wqkh, wqkl, (size_t)(N4_WQ + j));     // Wk rows after
    } else if ((j -= N4_WK) < N4_WV) {
        h_single4(wv[j], wvf, (size_t)j);
    } else {
        j -= N4_WV;
        h_single4(wo[j], wof, (size_t)j);
    }
}

// swizzle for 64B-pitch stages
__device__ __forceinline__ uint32_t gsw(int r, int c) {   // c = 16B chunk 0..3
    return (uint32_t)(r * 64 + ((c ^ (r & 3)) * 16));
}

// ================= bf16 3-term GEMM (combined Q|K projection) ==============
#define G_MATA 4096
#define G_MATB 8192
#define G_A_H 0
#define G_A_L 4096
#define G_B_H 8192
#define G_B_L 16384
#define G_SS  24576
#define SMEM_GEMM (3 * G_SS)

__global__ __launch_bounds__(128, 3)
void gemm_bf16x3(const __nv_bfloat16* __restrict__ Ah, const __nv_bfloat16* __restrict__ Al,
                 const __nv_bfloat16* __restrict__ Bh, const __nv_bfloat16* __restrict__ Bl,
                 float* __restrict__ C, int N, int K) {
    extern __shared__ char smemc[];
    const uint32_t sb = smem_u32(smemc);
    const int tid = threadIdx.x;
    const int lane = tid & 31;
    const int w = tid >> 5;
    const int wm = (w >> 1) * 32;
    const int wn = (w & 1) * 64;
    const int bm = blockIdx.y * 64;
    const int bn = blockIdx.x * 128;
    const int nkb = K / 32;

    auto load_stage = [&](int s, int kblk) {
        const uint32_t st = sb + s * G_SS;
#pragma unroll
        for (int m = 0; m < 2; m++) {
            const __nv_bfloat16* src = (m ? Al : Ah) + (size_t)bm * K + kblk;
            const uint32_t dstb = st + G_A_H + m * G_MATA;
#pragma unroll
            for (int i = 0; i < 2; i++) {
                int flat = tid + i * 128;
                int r = flat >> 2, c = flat & 3;
                CP_ASYNC16(dstb + gsw(r, c), src + (size_t)r * K + c * 8);
            }
        }
#pragma unroll
        for (int m = 0; m < 2; m++) {
            const __nv_bfloat16* src = (m ? Bl : Bh) + (size_t)bn * K + kblk;
            const uint32_t dstb = st + G_B_H + m * G_MATB;
#pragma unroll
            for (int i = 0; i < 4; i++) {
                int flat = tid + i * 128;
                int r = flat >> 2, c = flat & 3;
                CP_ASYNC16(dstb + gsw(r, c), src + (size_t)r * K + c * 8);
            }
        }
    };

    float acc[2][8][4];
#pragma unroll
    for (int i = 0; i < 2; i++)
#pragma unroll
        for (int j = 0; j < 8; j++)
#pragma unroll
            for (int q = 0; q < 4; q++) acc[i][j][q] = 0.f;

    load_stage(0, 0);  CP_COMMIT();
    load_stage(1, 32); CP_COMMIT();
    load_stage(2, 64); CP_COMMIT();

    const int aro = (lane & 7) + 8 * ((lane >> 3) & 1);
    const int acs = (lane >> 4);
    const int bro = (lane & 7) + 8 * ((lane >> 4) & 1);
    const int bcs = ((lane >> 3) & 1);

    int s = 0;
    for (int kb = 0; kb < nkb; kb++) {
        CP_WAIT1();
        __syncthreads();
        if (kb >= 1 && kb + 2 < nkb) load_stage((kb + 2) % 3, (kb + 2) * 32);
        if (kb >= 1) CP_COMMIT();
        const uint32_t st = sb + s * G_SS;

#pragma unroll
        for (int kk = 0; kk < 2; kk++) {
            uint32_t ah[2][4], al[2][4];
#pragma unroll
            for (int i = 0; i < 2; i++) {
                int r = wm + i * 16 + aro;
                uint32_t ab = st + G_A_H + gsw(r, kk * 2 + acs);
                ldsm4(ah[i], ab);
                ldsm4(al[i], ab + G_MATA);
            }
#pragma unroll
            for (int jp = 0; jp < 4; jp++) {
                uint32_t bh[4], bl[4];
                int r = wn + jp * 16 + bro;
                uint32_t bb = st + G_B_H + gsw(r, kk * 2 + bcs);
                ldsm4(bh, bb);
                ldsm4(bl, bb + G_MATB);
#pragma unroll
                for (int i = 0; i < 2; i++) {
                    mma16816(acc[i][2 * jp],     ah[i], bh[0], bh[1]);
                    mma16816(acc[i][2 * jp + 1], ah[i], bh[2], bh[3]);
                }
#pragma unroll
                for (int i = 0; i < 2; i++) {
                    mma16816(acc[i][2 * jp],     ah[i], bl[0], bl[1]);
                    mma16816(acc[i][2 * jp + 1], ah[i], bl[2], bl[3]);
                }
#pragma unroll
                for (int i = 0; i < 2; i++) {
                    mma16816(acc[i][2 * jp],     al[i], bh[0], bh[1]);
                    mma16816(acc[i][2 * jp + 1], al[i], bh[2], bh[3]);
                }
            }
        }
        s = (s == 2) ? 0 : s + 1;
    }

    const int lr = lane >> 2;
    const int lc = lane & 3;
#pragma unroll
    for (int i = 0; i < 2; i++) {
        const int r0 = bm + wm + i * 16 + lr;
#pragma unroll
        for (int j = 0; j < 8; j++) {
            const int c0 = bn + wn + j * 8 + lc * 2;
            *(float2*)(C + (size_t)r0 * N + c0) = make_float2(acc[i][j][0], acc[i][j][1]);
            *(float2*)(C + (size_t)(r0 + 8) * N + c0) = make_float2(acc[i][j][2], acc[i][j][3]);
        }
    }
}

// ============ fp16 2-term GEMM (V / output projections) ====================
#define F_A_H 0
#define F_A_L 4096
#define F_B   8192
#define F_SS  16384
#define SMEM_GEMM_F (3 * F_SS)

__global__ __launch_bounds__(128, 3)
void gemm_fp16x2(const __half* __restrict__ Ah, const __half* __restrict__ Al,
                 const __half* __restrict__ B,
                 float* __restrict__ C, int N, int K) {
    extern __shared__ char smemc[];
    const uint32_t sb = smem_u32(smemc);
    const int tid = threadIdx.x;
    const int lane = tid & 31;
    const int w = tid >> 5;
    const int wm = (w >> 1) * 32;
    const int wn = (w & 1) * 64;
    const int bm = blockIdx.y * 64;
    const int bn = blockIdx.x * 128;
    const int nkb = K / 32;

    auto load_stage = [&](int s, int kblk) {
        const uint32_t st = sb + s * F_SS;
#pragma unroll
        for (int m = 0; m < 2; m++) {
            const __half* src = (m ? Al : Ah) + (size_t)bm * K + kblk;
            const uint32_t dstb = st + F_A_H + m * 4096;
#pragma unroll
            for (int i = 0; i < 2; i++) {
                int flat = tid + i * 128;
                int r = flat >> 2, c = flat & 3;
                CP_ASYNC16(dstb + gsw(r, c), src + (size_t)r * K + c * 8);
            }
        }
        {
            const __half* src = B + (size_t)bn * K + kblk;
            const uint32_t dstb = st + F_B;
#pragma unroll
            for (int i = 0; i < 4; i++) {
                int flat = tid + i * 128;
                int r = flat >> 2, c = flat & 3;
                CP_ASYNC16(dstb + gsw(r, c), src + (size_t)r * K + c * 8);
            }
        }
    };

    float acc[2][8][4];
#pragma unroll
    for (int i = 0; i < 2; i++)
#pragma unroll
        for (int j = 0; j < 8; j++)
#pragma unroll
            for (int q = 0; q < 4; q++) acc[i][j][q] = 0.f;

    load_stage(0, 0);  CP_COMMIT();
    load_stage(1, 32); CP_COMMIT();
    load_stage(2, 64); CP_COMMIT();

    const int aro = (lane & 7) + 8 * ((lane >> 3) & 1);
    const int acs = (lane >> 4);
    const int bro = (lane & 7) + 8 * ((lane >> 4) & 1);
    const int bcs = ((lane >> 3) & 1);

    int s = 0;
    for (int kb = 0; kb < nkb; kb++) {
        CP_WAIT1();
        __syncthreads();
        if (kb >= 1 && kb + 2 < nkb) load_stage((kb + 2) % 3, (kb + 2) * 32);
        if (kb >= 1) CP_COMMIT();
        const uint32_t st = sb + s * F_SS;

#pragma unroll
        for (int kk = 0; kk < 2; kk++) {
            uint32_t ah[2][4], al[2][4];
#pragma unroll
            for (int i = 0; i < 2; i++) {
                int r = wm + i * 16 + aro;
                uint32_t ab = st + F_A_H + gsw(r, kk * 2 + acs);
                ldsm4(ah[i], ab);
                ldsm4(al[i], ab + 4096);
            }
#pragma unroll
            for (int jp = 0; jp < 4; jp++) {
                uint32_t bh[4];
                int r = wn + jp * 16 + bro;
                ldsm4(bh, st + F_B + gsw(r, kk * 2 + bcs));
#pragma unroll
                for (int i = 0; i < 2; i++) {
                    mma16816h(acc[i][2 * jp],     ah[i], bh[0], bh[1]);
                    mma16816h(acc[i][2 * jp + 1], ah[i], bh[2], bh[3]);
                }
#pragma unroll
                for (int i = 0; i < 2; i++) {
                    mma16816h(acc[i][2 * jp],     al[i], bh[0], bh[1]);
                    mma16816h(acc[i][2 * jp + 1], al[i], bh[2], bh[3]);
                }
            }
        }
        s = (s == 2) ? 0 : s + 1;
    }

    const int lr = lane >> 2;
    const int lc = lane & 3;
#pragma unroll
    for (int i = 0; i < 2; i++) {
        const int r0 = bm + wm + i * 16 + lr;
#pragma unroll
        for (int j = 0; j < 8; j++) {
            const int c0 = bn + wn + j * 8 + lc * 2;
            *(float2*)(C + (size_t)r0 * N + c0) = make_float2(acc[i][j][0], acc[i][j][1]);
            *(float2*)(C + (size_t)(r0 + 8) * N + c0) = make_float2(acc[i][j][2], acc[i][j][3]);
        }
    }
}

// ======= RMSNorm + RoPE; Q/K -> bf16 hi/lo, V -> fp16 single ================
__global__ __launch_bounds__(256)
void norm_rope2(const float* __restrict__ QKp, const float* __restrict__ Vp,
                const float* __restrict__ cosb, const float* __restrict__ sinb,
                const float* __restrict__ qw, const float* __restrict__ kw,
                __nv_bfloat16* __restrict__ Qrh, __nv_bfloat16* __restrict__ Qrl,
                __nv_bfloat16* __restrict__ Krh, __nv_bfloat16* __restrict__ Krl,
                __half* __restrict__ Vrf) {
    const int s = blockIdx.x;
    const int d = threadIdx.x;

    __shared__ float cs[HD], sn[HD], qws[HD], kws[HD], red[8], ysh[HD];
    cs[d]  = cosb[(size_t)s * HD + d];
    sn[d]  = sinb[(size_t)s * HD + d];
    qws[d] = qw[d];
    kws[d] = kw[d];
    __syncthreads();

    for (int hh = 0; hh < HQ + 2 * HKV; hh++) {
        const float* src;
        __nv_bfloat16 *dsth = nullptr, *dstl = nullptr;
        __half* dstv = nullptr;
        const float* wv = nullptr;
        bool do_rope = false;

        if (hh < HQ) {
            src = QKp + (size_t)s * NQK + hh * HD;
            dsth = Qrh + ((size_t)hh * S_LEN + s) * HD;
            dstl = Qrl + ((size_t)hh * S_LEN + s) * HD;
            wv = qws; do_rope = true;
        } else if (hh < HQ + HKV) {
            int h = hh - HQ;
            src = QKp + (size_t)s * NQK + HQ * HD + h * HD;
            dsth = Krh + ((size_t)h * S_LEN + s) * HD;
            dstl = Krl + ((size_t)h * S_LEN + s) * HD;
            wv = kws; do_rope = true;
        } else {
            int h = hh - HQ - HKV;
            src = Vp + (size_t)s * (HKV * HD) + h * HD;
            dstv = Vrf + ((size_t)h * S_LEN + s) * HD;
        }

        float x = src[d];
        float v = x * x;
#pragma unroll
        for (int off = 16; off > 0; off >>= 1)
            v += __shfl_xor_sync(0xffffffffu, v, off);
        if ((d & 31) == 0) red[d >> 5] = v;
        __syncthreads();
        float tot = 0.f;
#pragma unroll
        for (int r = 0; r < 8; r++) tot += red[r];

        float rms = rsqrtf(tot * (1.0f / HD) + 1e-6f);
        float y = x * rms;
        if (wv) y *= wv[d];

        if (do_rope) {
            ysh[d] = y;
            __syncthreads();
            float rot = (d < HD / 2) ? -ysh[d + HD / 2] : ysh[d - HD / 2];
            y = y * cs[d] + rot * sn[d];
        }
        if (dstv) {
            dstv[d] = __float2half_rn(y);
        } else {
            __nv_bfloat16 hb = __float2bfloat16(y);
            dsth[d] = hb;
            dstl[d] = __float2bfloat16(y - __bfloat162float(hb));
        }
        __syncthreads();
    }
}

// ================= HMMA flash attention (sliding window + softcap) =========
// QK: bf16 3-term. PV: fp16 2-term (P exact hi/lo x V single fp16).
#define APITCH 528
#define AQH_OFF 0
#define AQL_OFF 33792
#define AKH_OFF 67584
#define AKL_OFF 101376
#define AVF_OFF 135168
#define APH_OFF 168960
#define APL_OFF 178176
#define ASTAT_OFF 187392
#define SMEM_ATTN 189184

__global__ __launch_bounds__(256, 1)
void attn_mma(const __nv_bfloat16* __restrict__ Qh, const __nv_bfloat16* __restrict__ Ql,
              const __nv_bfloat16* __restrict__ Kh, const __nv_bfloat16* __restrict__ Kl,
              const __half* __restrict__ Vf,
              __half* __restrict__ AOh, __half* __restrict__ AOl) {
    extern __shared__ char smemc[];
    const uint32_t sb = smem_u32(smemc);
    const int tid = threadIdx.x;
    const int lane = tid & 31;
    const int w = tid >> 5;
    const int h = blockIdx.y;
    const int q0 = blockIdx.x * 64;

    const __nv_bfloat16* qhp = Qh + ((size_t)h * S_LEN + q0) * HD;
    const __nv_bfloat16* qlp = Ql + ((size_t)h * S_LEN + q0) * HD;
    const __nv_bfloat16* khp = Kh + (size_t)(h >> 1) * S_LEN * HD;
    const __nv_bfloat16* klp = Kl + (size_t)(h >> 1) * S_LEN * HD;
    const __half* vfp = Vf + (size_t)(h >> 1) * S_LEN * HD;

    float* marr  = (float*)(smemc + ASTAT_OFF);
    float* larr  = marr + 64;
    float* alpha = marr + 128;
    float* pm0   = marr + 192;
    float* pm1   = marr + 256;
    float* ps0   = marr + 320;
    float* ps1   = marr + 384;

    if (tid < 64) { marr[tid] = -1e30f; larr[tid] = 0.f; }

    auto cpQ = [&](uint32_t off, const __nv_bfloat16* src) {
#pragma unroll
        for (int i = 0; i < 8; i++) {
            int flat = tid + i * 256;
            int r = flat >> 5, c = flat & 31;
            CP_ASYNC16(sb + off + r * APITCH + c * 16, src + (size_t)r * HD + c * 8);
        }
    };
    auto cpT = [&](uint32_t off, const __nv_bfloat16* base, int kt) {
#pragma unroll
        for (int i = 0; i < 8; i++) {
            int flat = tid + i * 256;
            int r = flat >> 5, c = flat & 31;
            CP_ASYNC16(sb + off + r * APITCH + c * 16, base + (size_t)(kt + r) * HD + c * 8);
        }
    };
    auto cpV = [&](int kt) {
#pragma unroll
        for (int i = 0; i < 8; i++) {
            int flat = tid + i * 256;
            int r = flat >> 5, c = flat & 31;
            CP_ASYNC16(sb + AVF_OFF + r * APITCH + c * 16, vfp + (size_t)(kt + r) * HD + c * 8);
        }
    };

    int klo = q0 - (WIN - 1);
    if (klo < 0) klo = 0;
    const int kt0 = klo & ~63;

    cpQ(AQH_OFF, qhp); cpQ(AQL_OFF, qlp);
    cpT(AKH_OFF, khp, kt0); cpT(AKL_OFF, klp, kt0);
    CP_COMMIT();

    float oacc[16][4];
#pragma unroll
    for (int i = 0; i < 16; i++)
#pragma unroll
        for (int q = 0; q < 4; q++) oacc[i][q] = 0.f;

    const int aro = (lane & 7) + 8 * ((lane >> 3) & 1);
    const int aco = (lane >> 4) * 16;
    const int bro = (lane & 7) + 8 * ((lane >> 4) & 1);
    const int bco = ((lane >> 3) & 1) * 16;
    const int R  = 16 * (w >> 1);
    const int Ch = 32 * (w & 1);
    const int Rp = 16 * (w & 3);
    const int Dq = 128 * (w >> 2);
    const int rl = lane >> 2;

    __syncthreads();

    for (int kt = kt0; kt <= q0; kt += 64) {
        cpV(kt);
        CP_COMMIT();
        CP_WAIT1();
        __syncthreads();

        // ---------------- QK ----------------
        float sacc[4][4];
#pragma unroll
        for (int i = 0; i < 4; i++)
#pragma unroll
            for (int q = 0; q < 4; q++) sacc[i][q] = 0.f;

#pragma unroll
        for (int ks = 0; ks < 16; ks++) {
            uint32_t aH[4], aL[4];
            uint32_t ab = sb + AQH_OFF + (R + aro) * APITCH + ks * 32 + aco;
            ldsm4(aH, ab);
            ldsm4(aL, ab + (AQL_OFF - AQH_OFF));
            uint32_t bH0[4], bL0[4], bH1[4], bL1[4];
            uint32_t bb0 = sb + AKH_OFF + (Ch + bro) * APITCH + ks * 32 + bco;
            uint32_t bb1 = sb + AKH_OFF + (Ch + 16 + bro) * APITCH + ks * 32 + bco;
            ldsm4(bH0, bb0);
            ldsm4(bL0, bb0 + (AKL_OFF - AKH_OFF));
            ldsm4(bH1, bb1);
            ldsm4(bL1, bb1 + (AKL_OFF - AKH_OFF));
            mma16816(sacc[0], aH, bH0[0], bH0[1]);
            mma16816(sacc[1], aH, bH0[2], bH0[3]);
            mma16816(sacc[2], aH, bH1[0], bH1[1]);
            mma16816(sacc[3], aH, bH1[2], bH1[3]);
            mma16816(sacc[0], aH, bL0[0], bL0[1]);
            mma16816(sacc[1], aH, bL0[2], bL0[3]);
            mma16816(sacc[2], aH, bL1[0], bL1[1]);
            mma16816(sacc[3], aH, bL1[2], bL1[3]);
            mma16816(sacc[0], aL, bH0[0], bH0[1]);
            mma16816(sacc[1], aL, bH0[2], bH0[3]);
            mma16816(sacc[2], aL, bH1[0], bH1[1]);
            mma16816(sacc[3], aL, bH1[2], bH1[3]);
        }

        const int rlo = R + rl, rhi = R + rl + 8;
        float mx0 = -1e30f, mx1 = -1e30f;
#pragma unroll
        for (int n8 = 0; n8 < 4; n8++) {
#pragma unroll
            for (int e = 0; e < 4; e++) {
                int row = (e < 2) ? rlo : rhi;
                int kg = kt + Ch + n8 * 8 + (lane & 3) * 2 + (e & 1);
                int qg = q0 + row;
                float s = softcap50(sacc[n8][e]);
                bool ok = (kg <= qg) && (qg - kg < WIN);
                s = ok ? s : -1e30f;
                sacc[n8][e] = s;
                if (e < 2) mx0 = fmaxf(mx0, s); else mx1 = fmaxf(mx1, s);
            }
        }
        mx0 = fmaxf(mx0, __shfl_xor_sync(0xffffffffu, mx0, 1));
        mx0 = fmaxf(mx0, __shfl_xor_sync(0xffffffffu, mx0, 2));
        mx1 = fmaxf(mx1, __shfl_xor_sync(0xffffffffu, mx1, 1));
        mx1 = fmaxf(mx1, __shfl_xor_sync(0xffffffffu, mx1, 2));
        if ((lane & 3) == 0) {
            float* pmh = (w & 1) ? pm1 : pm0;
            pmh[rlo] = mx0; pmh[rhi] = mx1;
        }
        __syncthreads();

        if (kt + 64 <= q0) { cpT(AKH_OFF, khp, kt + 64); cpT(AKL_OFF, klp, kt + 64); }
        CP_COMMIT();

        if (tid < 64) {
            float mo = marr[tid];
            float mn = fmaxf(mo, fmaxf(pm0[tid], pm1[tid]));
            alpha[tid] = (mn > -1e29f) ? __expf(mo - mn) : 1.f;
            marr[tid] = mn;
        }
        __syncthreads();

        {
            float mn0 = marr[rlo], mn1 = marr[rhi];
            float sum0 = 0.f, sum1 = 0.f;
#pragma unroll
            for (int n8 = 0; n8 < 4; n8++) {
                float p0 = (sacc[n8][0] > -1e29f) ? __expf(sacc[n8][0] - mn0) : 0.f;
                float p1 = (sacc[n8][1] > -1e29f) ? __expf(sacc[n8][1] - mn0) : 0.f;
                float p2 = (sacc[n8][2] > -1e29f) ? __expf(sacc[n8][2] - mn1) : 0.f;
                float p3 = (sacc[n8][3] > -1e29f) ? __expf(sacc[n8][3] - mn1) : 0.f;
                sum0 += p0 + p1; sum1 += p2 + p3;
                int cb = (Ch + n8 * 8 + (lane & 3) * 2) * 2;
                uint32_t hlo = pack2h(p0, p1);
                uint32_t hhi = pack2h(p2, p3);
                __half2 hv0 = *(__half2*)&hlo;
                __half2 hv1 = *(__half2*)&hhi;
                *(uint32_t*)(smemc + APH_OFF + rlo * 144 + cb) = hlo;
                *(uint32_t*)(smemc + APH_OFF + rhi * 144 + cb) = hhi;
                *(uint32_t*)(smemc + APL_OFF + rlo * 144 + cb) =
                    pack2h(p0 - __half2float(hv0.x), p1 - __half2float(hv0.y));
                *(uint32_t*)(smemc + APL_OFF + rhi * 144 + cb) =
                    pack2h(p2 - __half2float(hv1.x), p3 - __half2float(hv1.y));
            }
            sum0 += __shfl_xor_sync(0xffffffffu, sum0, 1);
            sum0 += __shfl_xor_sync(0xffffffffu, sum0, 2);
            sum1 += __shfl_xor_sync(0xffffffffu, sum1, 1);
            sum1 += __shfl_xor_sync(0xffffffffu, sum1, 2);
            if ((lane & 3) == 0) {
                float* psh = (w & 1) ? ps1 : ps0;
                psh[rlo] = sum0; psh[rhi] = sum1;
            }
        }
        __syncthreads();
        if (tid < 64) larr[tid] = alpha[tid] * larr[tid] + ps0[tid] + ps1[tid];
        CP_WAIT1();
        __syncthreads();

        // ---------------- PV (fp16 2-term) ----------------
        {
            float a0 = alpha[Rp + rl], a1 = alpha[Rp + 8 + rl];
#pragma unroll
            for (int n8 = 0; n8 < 16; n8++) {
                oacc[n8][0] *= a0; oacc[n8][1] *= a0;
                oacc[n8][2] *= a1; oacc[n8][3] *= a1;
            }
            const int vco = ((lane >> 4) & 1) * 8;
            const int vrw = (lane & 7) + 8 * ((lane >> 3) & 1);
#pragma unroll
            for (int ks = 0; ks < 4; ks++) {
                uint32_t pH[4], pL[4];
                uint32_t pb = sb + APH_OFF + (Rp + aro) * 144 + ks * 32 + aco;
                ldsm4(pH, pb);
                ldsm4(pL, pb + (APL_OFF - APH_OFF));
#pragma unroll
                for (int dt = 0; dt < 8; dt += 2) {
                    uint32_t vH0[4], vH1[4];
                    uint32_t vb0 = sb + AVF_OFF + (ks * 16 + vrw) * APITCH +
                                   (Dq + dt * 16 + vco) * 2;
                    uint32_t vb1 = vb0 + 32;
                    ldsm4t(vH0, vb0);
                    ldsm4t(vH1, vb1);
                    mma16816h(oacc[2 * dt],     pH, vH0[0], vH0[1]);
                    mma16816h(oacc[2 * dt + 1], pH, vH0[2], vH0[3]);
                    mma16816h(oacc[2 * dt + 2], pH, vH1[0], vH1[1]);
                    mma16816h(oacc[2 * dt + 3], pH, vH1[2], vH1[3]);
                    mma16816h(oacc[2 * dt],     pL, vH0[0], vH0[1]);
                    mma16816h(oacc[2 * dt + 1], pL, vH0[2], vH0[3]);
                    mma16816h(oacc[2 * dt + 2], pL, vH1[0], vH1[1]);
                    mma16816h(oacc[2 * dt + 3], pL, vH1[2], vH1[3]);
                }
            }
        }
        __syncthreads();
    }

    // output: fp16 hi/lo, [S][HQ*HD]
    {
        float inv0 = 1.0f / larr[Rp + rl];
        float inv1 = 1.0f / larr[Rp + 8 + rl];
        const int r0 = q0 + Rp + rl;
#pragma unroll
        for (int n8 = 0; n8 < 16; n8++) {
            int col = h * HD + Dq + n8 * 8 + (lane & 3) * 2;
            float o0 = oacc[n8][0] * inv0, o1 = oacc[n8][1] * inv0;
            float o2 = oacc[n8][2] * inv1, o3 = oacc[n8][3] * inv1;
            uint32_t h0 = pack2h(o0, o1);
            __half2 hv0 = *(__half2*)&h0;
            uint32_t l0 = pack2h(o0 - __half2float(hv0.x), o1 - __half2float(hv0.y));
            uint32_t h1 = pack2h(o2, o3);
            __half2 hv1 = *(__half2*)&h1;
            uint32_t l1 = pack2h(o2 - __half2float(hv1.x), o3 - __half2float(hv1.y));
            *(uint32_t*)(AOh + (size_t)r0 * (HQ * HD) + col) = h0;
            *(uint32_t*)(AOl + (size_t)r0 * (HQ * HD) + col) = l0;
            *(uint32_t*)(AOh + (size_t)(r0 + 8) * (HQ * HD) + col) = h1;
            *(uint32_t*)(AOl + (size_t)(r0 + 8) * (HQ * HD) + col) = l1;
        }
    }
}

// ================= launch =================
extern "C" void kernel_launch(void* const* d_in, const int* in_sizes, int n_in,
                              void* d_out, int out_size) {
    const float* hidden = (const float*)d_in[0];
    const float* cosb   = (const float*)d_in[1];
    const float* sinb   = (const float*)d_in[2];
    // d_in[3] = attention_mask (sliding window, implemented analytically)
    const float* Wq = (const float*)d_in[4];
    const float* Wk = (const float*)d_in[5];
    const float* Wv = (const float*)d_in[6];
    const float* Wo = (const float*)d_in[7];
    const float* qw = (const float*)d_in[8];
    const float* kw = (const float*)d_in[9];
    float* out = (float*)d_out;

    float *QKp, *Vp;
    cudaGetSymbolAddress((void**)&QKp, g_QKp);
    cudaGetSymbolAddress((void**)&Vp, g_Vp);

    __nv_bfloat16 *hidh, *hidl, *wqkh, *wqkl;
    __half *hidfh, *hidfl, *wvf, *wof, *aofh, *aofl, *vrf;
    __nv_bfloat16 *qrh, *qrl, *krh, *krl;
    cudaGetSymbolAddress((void**)&hidh, g_hid_h);
    cudaGetSymbolAddress((void**)&hidl, g_hid_l);
    cudaGetSymbolAddress((void**)&hidfh, g_hid_fh);
    cudaGetSymbolAddress((void**)&hidfl, g_hid_fl);
    cudaGetSymbolAddress((void**)&wqkh, g_wqk_h);
    cudaGetSymbolAddress((void**)&wqkl, g_wqk_l);
    cudaGetSymbolAddress((void**)&wvf, g_wv_f);
    cudaGetSymbolAddress((void**)&wof, g_wo_f);
    cudaGetSymbolAddress((void**)&aofh, g_ao_fh);
    cudaGetSymbolAddress((void**)&aofl, g_ao_fl);
    cudaGetSymbolAddress((void**)&qrh, g_qr_h);
    cudaGetSymbolAddress((void**)&qrl, g_qr_l);
    cudaGetSymbolAddress((void**)&krh, g_kr_h);
    cudaGetSymbolAddress((void**)&krl, g_kr_l);
    cudaGetSymbolAddress((void**)&vrf, g_vr_f);

    cudaFuncSetAttribute((const void*)gemm_bf16x3,
                         cudaFuncAttributeMaxDynamicSharedMemorySize, SMEM_GEMM);
    cudaFuncSetAttribute((const void*)gemm_fp16x2,
                         cudaFuncAttributeMaxDynamicSharedMemorySize, SMEM_GEMM_F);
    cudaFuncSetAttribute((const void*)attn_mma,
                         cudaFuncAttributeMaxDynamicSharedMemorySize, SMEM_ATTN);

    // fused conversions (one launch)
    cvt_all<<<(N4_TOT + 255) / 256, 256>>>(
        (const float4*)hidden, (const float4*)Wq, (const float4*)Wk,
        (const float4*)Wv, (const float4*)Wo,
        hidh, hidl, hidfh, hidfl, wqkh, wqkl, wvf, wof);

    // combined Q|K projection: bf16 3-term, N=3072 (better wave packing)
    gemm_bf16x3<<<dim3(NQK / 128, 64), 128, SMEM_GEMM>>>(hidh, hidl, wqkh, wqkl,
                                                         QKp, NQK, H_DIM);
    // V projection: fp16 2-term
    gemm_fp16x2<<<dim3(8, 64), 128, SMEM_GEMM_F>>>(hidfh, hidfl, wvf, Vp, HKV * HD, H_DIM);

    // RMSNorm + RoPE: Q/K -> bf16 hi/lo, V -> fp16
    norm_rope2<<<S_LEN, 256>>>(QKp, Vp, cosb, sinb, qw, kw,
                               qrh, qrl, krh, krl, vrf);

    // tensor-core flash attention -> fp16 hi/lo AO
    attn_mma<<<dim3(S_LEN / 64, HQ), 256, SMEM_ATTN>>>(qrh, qrl, krh, krl, vrf, aofh, aofl);

    // output projection: fp16 2-term
    gemm_fp16x2<<<dim3(16, 64), 128, SMEM_GEMM_F>>>(aofh, aofl, wof, out, H_DIM, H_DIM);
}

// round 14
// speedup vs baseline: 1.3335x; 1.0483x over previous
#include <cuda_runtime.h>
#include <cuda_bf16.h>
#include <cuda_fp16.h>
#include <math.h>
#include <stdint.h>

#define S_LEN 4096
#define H_DIM 2048
#define HQ 8
#define HKV 4
#define HD 256
#define WIN 1024
#define NQK (HQ * HD + HKV * HD)   // 3072 combined Q+K output width

// ================= portable PTX helpers (baseline ISA only) =================
__device__ __forceinline__ uint32_t smem_u32(const void* p) {
    uint32_t a;
    asm("{ .reg .u64 t; cvta.to.shared.u64 t, %1; cvt.u32.u64 %0, t; }"
        : "=r"(a) : "l"(p));
    return a;
}

#define CP_ASYNC16(dst_u32, src_ptr) \
    asm volatile("cp.async.cg.shared.global [%0], [%1], 16;" \
                 :: "r"(dst_u32), "l"(src_ptr) : "memory")
#define CP_COMMIT() asm volatile("cp.async.commit_group;" ::: "memory")
#define CP_WAIT1()  asm volatile("cp.async.wait_group 1;" ::: "memory")

__device__ __forceinline__ void mma16816(float* d, const uint32_t* a,
                                         uint32_t b0, uint32_t b1) {
    asm volatile(
        "mma.sync.aligned.m16n8k16.row.col.f32.bf16.bf16.f32 "
        "{%0,%1,%2,%3}, {%4,%5,%6,%7}, {%8,%9}, {%0,%1,%2,%3};"
        : "+f"(d[0]), "+f"(d[1]), "+f"(d[2]), "+f"(d[3])
        : "r"(a[0]), "r"(a[1]), "r"(a[2]), "r"(a[3]), "r"(b0), "r"(b1));
}

__device__ __forceinline__ void mma16816h(float* d, const uint32_t* a,
                                          uint32_t b0, uint32_t b1) {
    asm volatile(
        "mma.sync.aligned.m16n8k16.row.col.f32.f16.f16.f32 "
        "{%0,%1,%2,%3}, {%4,%5,%6,%7}, {%8,%9}, {%0,%1,%2,%3};"
        : "+f"(d[0]), "+f"(d[1]), "+f"(d[2]), "+f"(d[3])
        : "r"(a[0]), "r"(a[1]), "r"(a[2]), "r"(a[3]), "r"(b0), "r"(b1));
}

__device__ __forceinline__ void ldsm4(uint32_t* r, uint32_t addr) {
    asm volatile("ldmatrix.sync.aligned.m8n8.x4.shared.b16 {%0,%1,%2,%3}, [%4];"
                 : "=r"(r[0]), "=r"(r[1]), "=r"(r[2]), "=r"(r[3]) : "r"(addr));
}
__device__ __forceinline__ void ldsm4t(uint32_t* r, uint32_t addr) {
    asm volatile("ldmatrix.sync.aligned.m8n8.x4.trans.shared.b16 {%0,%1,%2,%3}, [%4];"
                 : "=r"(r[0]), "=r"(r[1]), "=r"(r[2]), "=r"(r[3]) : "r"(addr));
}

__device__ __forceinline__ uint32_t pack2bf(float a, float b) {
    __nv_bfloat162 t = __floats2bfloat162_rn(a, b);
    return *(uint32_t*)&t;
}
__device__ __forceinline__ uint32_t pack2h(float a, float b) {
    __half2 t = __floats2half2_rn(a, b);
    return *(uint32_t*)&t;
}

// inf-safe fast softcap: 50*tanh(x/50)
__device__ __forceinline__ float softcap50(float x) {
    float e = __expf(x * 0.04f);
    return 50.f * (1.f - __fdividef(2.f, e + 1.f));
}

// ================= scratch (device globals) =================
__device__ float g_QKp[S_LEN * NQK];
__device__ float g_Vp[S_LEN * (HKV * HD)];

__device__ __nv_bfloat16 g_hid_h[S_LEN * H_DIM];
__device__ __nv_bfloat16 g_hid_l[S_LEN * H_DIM];
__device__ __half        g_hid_fh[S_LEN * H_DIM];
__device__ __half        g_hid_fl[S_LEN * H_DIM];
__device__ __nv_bfloat16 g_wqk_h[NQK * H_DIM];
__device__ __nv_bfloat16 g_wqk_l[NQK * H_DIM];
__device__ __half        g_wv_f[HKV * HD * H_DIM];
__device__ __half        g_wo_f[H_DIM * HQ * HD];
__device__ __half        g_ao_fh[S_LEN * HQ * HD];
__device__ __half        g_ao_fl[S_LEN * HQ * HD];

__device__ __nv_bfloat16 g_qr_h[HQ * S_LEN * HD];
__device__ __nv_bfloat16 g_qr_l[HQ * S_LEN * HD];
__device__ __nv_bfloat16 g_kr_h[HKV * S_LEN * HD];
__device__ __nv_bfloat16 g_kr_l[HKV * S_LEN * HD];
__device__ __half        g_vr_f[HKV * S_LEN * HD];

// ====== fused cvt (4x ILP) ======
#define N4_HID (S_LEN * H_DIM / 4)
#define N4_WQ  (HQ * HD * H_DIM / 4)
#define N4_WK  (HKV * HD * H_DIM / 4)
#define N4_WV  (HKV * HD * H_DIM / 4)
#define N4_WO  (H_DIM * HQ * HD / 4)
#define N4_TOT (N4_HID + N4_WQ + N4_WK + N4_WV + N4_WO)
#define CVT_THREADS (N4_TOT / 4)

__device__ __forceinline__ void bf_split4(float4 v, __nv_bfloat16* hi,
                                          __nv_bfloat16* lo, size_t j) {
    union { ushort4 u; __nv_bfloat16 b[4]; } H, L;
    H.b[0] = __float2bfloat16(v.x);
    H.b[1] = __float2bfloat16(v.y);
    H.b[2] = __float2bfloat16(v.z);
    H.b[3] = __float2bfloat16(v.w);
    L.b[0] = __float2bfloat16(v.x - __bfloat162float(H.b[0]));
    L.b[1] = __float2bfloat16(v.y - __bfloat162float(H.b[1]));
    L.b[2] = __float2bfloat16(v.z - __bfloat162float(H.b[2]));
    L.b[3] = __float2bfloat16(v.w - __bfloat162float(H.b[3]));
    *(ushort4*)(hi + 4 * j) = H.u;
    *(ushort4*)(lo + 4 * j) = L.u;
}

__device__ __forceinline__ void h_split4(float4 v, __half* hi, __half* lo, size_t j) {
    union { ushort4 u; __half b[4]; } H, L;
    H.b[0] = __float2half_rn(v.x);
    H.b[1] = __float2half_rn(v.y);
    H.b[2] = __float2half_rn(v.z);
    H.b[3] = __float2half_rn(v.w);
    L.b[0] = __float2half_rn(v.x - __half2float(H.b[0]));
    L.b[1] = __float2half_rn(v.y - __half2float(H.b[1]));
    L.b[2] = __float2half_rn(v.z - __half2float(H.b[2]));
    L.b[3] = __float2half_rn(v.w - __half2float(H.b[3]));
    *(ushort4*)(hi + 4 * j) = H.u;
    *(ushort4*)(lo + 4 * j) = L.u;
}

__device__ __forceinline__ void h_single4(float4 v, __half* dst, size_t j) {
    union { ushort4 u; __half b[4]; } H;
    H.b[0] = __float2half_rn(v.x); H.b[1] = __float2half_rn(v.y);
    H.b[2] = __float2half_rn(v.z); H.b[3] = __float2half_rn(v.w);
    *(ushort4*)(dst + 4 * j) = H.u;
}

__global__ __launch_bounds__(256)
void cvt_all(const float4* __restrict__ hid, const float4* __restrict__ wq,
             const float4* __restrict__ wk, const float4* __restrict__ wv,
             const float4* __restrict__ wo,
             __nv_bfloat16* __restrict__ hidh, __nv_bfloat16* __restrict__ hidl,
             __half* __restrict__ hidfh, __half* __restrict__ hidfl,
             __nv_bfloat16* __restrict__ wqkh, __nv_bfloat16* __restrict__ wqkl,
             __half* __restrict__ wvf, __half* __restrict__ wof) {
    int t = blockIdx.x * blockDim.x + threadIdx.x;
    if (t >= CVT_THREADS) return;
#pragma unroll
    for (int r = 0; r < 4; r++) {
        int i = t + r * CVT_THREADS;
        int j = i;
        if (j < N4_HID) {
            float4 v = hid[j];
            bf_split4(v, hidh, hidl, (size_t)j);
            h_split4(v, hidfh, hidfl, (size_t)j);
        } else if ((j -= N4_HID) < N4_WQ) {
            bf_split4(wq[j], wqkh, wqkl, (size_t)j);
        } else if ((j -= N4_WQ) < N4_WK) {
            bf_split4(wk[j], wqkh, wqkl, (size_t)(N4_WQ + j));
        } else if ((j -= N4_WK) < N4_WV) {
            h_single4(wv[j], wvf, (size_t)j);
        } else {
            j -= N4_WV;
            h_single4(wo[j], wof, (size_t)j);
        }
    }
}

// swizzle for 64B-pitch stages
__device__ __forceinline__ uint32_t gsw(int r, int c) {
    return (uint32_t)(r * 64 + ((c ^ (r & 3)) * 16));
}

// ================= bf16 3-term GEMM (combined Q|K projection) ==============
#define G_MATA 4096
#define G_MATB 8192
#define G_A_H 0
#define G_A_L 4096
#define G_B_H 8192
#define G_B_L 16384
#define G_SS  24576
#define SMEM_GEMM (3 * G_SS)

__global__ __launch_bounds__(128, 3)
void gemm_bf16x3(const __nv_bfloat16* __restrict__ Ah, const __nv_bfloat16* __restrict__ Al,
                 const __nv_bfloat16* __restrict__ Bh, const __nv_bfloat16* __restrict__ Bl,
                 float* __restrict__ C, int N, int K) {
    extern __shared__ char smemc[];
    const uint32_t sb = smem_u32(smemc);
    const int tid = threadIdx.x;
    const int lane = tid & 31;
    const int w = tid >> 5;
    const int wm = (w >> 1) * 32;
    const int wn = (w & 1) * 64;
    const int bm = blockIdx.y * 64;
    const int bn = blockIdx.x * 128;
    const int nkb = K / 32;

    auto load_stage = [&](int s, int kblk) {
        const uint32_t st = sb + s * G_SS;
#pragma unroll
        for (int m = 0; m < 2; m++) {
            const __nv_bfloat16* src = (m ? Al : Ah) + (size_t)bm * K + kblk;
            const uint32_t dstb = st + G_A_H + m * G_MATA;
#pragma unroll
            for (int i = 0; i < 2; i++) {
                int flat = tid + i * 128;
                int r = flat >> 2, c = flat & 3;
                CP_ASYNC16(dstb + gsw(r, c), src + (size_t)r * K + c * 8);
            }
        }
#pragma unroll
        for (int m = 0; m < 2; m++) {
            const __nv_bfloat16* src = (m ? Bl : Bh) + (size_t)bn * K + kblk;
            const uint32_t dstb = st + G_B_H + m * G_MATB;
#pragma unroll
            for (int i = 0; i < 4; i++) {
                int flat = tid + i * 128;
                int r = flat >> 2, c = flat & 3;
                CP_ASYNC16(dstb + gsw(r, c), src + (size_t)r * K + c * 8);
            }
        }
    };

    float acc[2][8][4];
#pragma unroll
    for (int i = 0; i < 2; i++)
#pragma unroll
        for (int j = 0; j < 8; j++)
#pragma unroll
            for (int q = 0; q < 4; q++) acc[i][j][q] = 0.f;

    load_stage(0, 0);  CP_COMMIT();
    load_stage(1, 32); CP_COMMIT();
    load_stage(2, 64); CP_COMMIT();

    const int aro = (lane & 7) + 8 * ((lane >> 3) & 1);
    const int acs = (lane >> 4);
    const int bro = (lane & 7) + 8 * ((lane >> 4) & 1);
    const int bcs = ((lane >> 3) & 1);

    int s = 0;
    for (int kb = 0; kb < nkb; kb++) {
        CP_WAIT1();
        __syncthreads();
        if (kb >= 1 && kb + 2 < nkb) load_stage((kb + 2) % 3, (kb + 2) * 32);
        if (kb >= 1) CP_COMMIT();
        const uint32_t st = sb + s * G_SS;

#pragma unroll
        for (int kk = 0; kk < 2; kk++) {
            uint32_t ah[2][4], al[2][4];
#pragma unroll
            for (int i = 0; i < 2; i++) {
                int r = wm + i * 16 + aro;
                uint32_t ab = st + G_A_H + gsw(r, kk * 2 + acs);
                ldsm4(ah[i], ab);
                ldsm4(al[i], ab + G_MATA);
            }
#pragma unroll
            for (int jp = 0; jp < 4; jp++) {
                uint32_t bh[4], bl[4];
                int r = wn + jp * 16 + bro;
                uint32_t bb = st + G_B_H + gsw(r, kk * 2 + bcs);
                ldsm4(bh, bb);
                ldsm4(bl, bb + G_MATB);
#pragma unroll
                for (int i = 0; i < 2; i++) {
                    mma16816(acc[i][2 * jp],     ah[i], bh[0], bh[1]);
                    mma16816(acc[i][2 * jp + 1], ah[i], bh[2], bh[3]);
                }
#pragma unroll
                for (int i = 0; i < 2; i++) {
                    mma16816(acc[i][2 * jp],     ah[i], bl[0], bl[1]);
                    mma16816(acc[i][2 * jp + 1], ah[i], bl[2], bl[3]);
                }
#pragma unroll
                for (int i = 0; i < 2; i++) {
                    mma16816(acc[i][2 * jp],     al[i], bh[0], bh[1]);
                    mma16816(acc[i][2 * jp + 1], al[i], bh[2], bh[3]);
                }
            }
        }
        s = (s == 2) ? 0 : s + 1;
    }

    const int lr = lane >> 2;
    const int lc = lane & 3;
#pragma unroll
    for (int i = 0; i < 2; i++) {
        const int r0 = bm + wm + i * 16 + lr;
#pragma unroll
        for (int j = 0; j < 8; j++) {
            const int c0 = bn + wn + j * 8 + lc * 2;
            *(float2*)(C + (size_t)r0 * N + c0) = make_float2(acc[i][j][0], acc[i][j][1]);
            *(float2*)(C + (size_t)(r0 + 8) * N + c0) = make_float2(acc[i][j][2], acc[i][j][3]);
        }
    }
}

// ============ fp16 2-term GEMM (V / output projections) ====================
#define F_A_H 0
#define F_A_L 4096
#define F_B   8192
#define F_SS  16384
#define SMEM_GEMM_F (3 * F_SS)

__global__ __launch_bounds__(128, 3)
void gemm_fp16x2(const __half* __restrict__ Ah, const __half* __restrict__ Al,
                 const __half* __restrict__ B,
                 float* __restrict__ C, int N, int K) {
    extern __shared__ char smemc[];
    const uint32_t sb = smem_u32(smemc);
    const int tid = threadIdx.x;
    const int lane = tid & 31;
    const int w = tid >> 5;
    const int wm = (w >> 1) * 32;
    const int wn = (w & 1) * 64;
    const int bm = blockIdx.y * 64;
    const int bn = blockIdx.x * 128;
    const int nkb = K / 32;

    auto load_stage = [&](int s, int kblk) {
        const uint32_t st = sb + s * F_SS;
#pragma unroll
        for (int m = 0; m < 2; m++) {
            const __half* src = (m ? Al : Ah) + (size_t)bm * K + kblk;
            const uint32_t dstb = st + F_A_H + m * 4096;
#pragma unroll
            for (int i = 0; i < 2; i++) {
                int flat = tid + i * 128;
                int r = flat >> 2, c = flat & 3;
                CP_ASYNC16(dstb + gsw(r, c), src + (size_t)r * K + c * 8);
            }
        }
        {
            const __half* src = B + (size_t)bn * K + kblk;
            const uint32_t dstb = st + F_B;
#pragma unroll
            for (int i = 0; i < 4; i++) {
                int flat = tid + i * 128;
                int r = flat >> 2, c = flat & 3;
                CP_ASYNC16(dstb + gsw(r, c), src + (size_t)r * K + c * 8);
            }
        }
    };

    float acc[2][8][4];
#pragma unroll
    for (int i = 0; i < 2; i++)
#pragma unroll
        for (int j = 0; j < 8; j++)
#pragma unroll
            for (int q = 0; q < 4; q++) acc[i][j][q] = 0.f;

    load_stage(0, 0);  CP_COMMIT();
    load_stage(1, 32); CP_COMMIT();
    load_stage(2, 64); CP_COMMIT();

    const int aro = (lane & 7) + 8 * ((lane >> 3) & 1);
    const int acs = (lane >> 4);
    const int bro = (lane & 7) + 8 * ((lane >> 4) & 1);
    const int bcs = ((lane >> 3) & 1);

    int s = 0;
    for (int kb = 0; kb < nkb; kb++) {
        CP_WAIT1();
        __syncthreads();
        if (kb >= 1 && kb + 2 < nkb) load_stage((kb + 2) % 3, (kb + 2) * 32);
        if (kb >= 1) CP_COMMIT();
        const uint32_t st = sb + s * F_SS;

#pragma unroll
        for (int kk = 0; kk < 2; kk++) {
            uint32_t ah[2][4], al[2][4];
#pragma unroll
            for (int i = 0; i < 2; i++) {
                int r = wm + i * 16 + aro;
                uint32_t ab = st + F_A_H + gsw(r, kk * 2 + acs);
                ldsm4(ah[i], ab);
                ldsm4(al[i], ab + 4096);
            }
#pragma unroll
            for (int jp = 0; jp < 4; jp++) {
                uint32_t bh[4];
                int r = wn + jp * 16 + bro;
                ldsm4(bh, st + F_B + gsw(r, kk * 2 + bcs));
#pragma unroll
                for (int i = 0; i < 2; i++) {
                    mma16816h(acc[i][2 * jp],     ah[i], bh[0], bh[1]);
                    mma16816h(acc[i][2 * jp + 1], ah[i], bh[2], bh[3]);
                }
#pragma unroll
                for (int i = 0; i < 2; i++) {
                    mma16816h(acc[i][2 * jp],     al[i], bh[0], bh[1]);
                    mma16816h(acc[i][2 * jp + 1], al[i], bh[2], bh[3]);
                }
            }
        }
        s = (s == 2) ? 0 : s + 1;
    }

    const int lr = lane >> 2;
    const int lc = lane & 3;
#pragma unroll
    for (int i = 0; i < 2; i++) {
        const int r0 = bm + wm + i * 16 + lr;
#pragma unroll
        for (int j = 0; j < 8; j++) {
            const int c0 = bn + wn + j * 8 + lc * 2;
            *(float2*)(C + (size_t)r0 * N + c0) = make_float2(acc[i][j][0], acc[i][j][1]);
            *(float2*)(C + (size_t)(r0 + 8) * N + c0) = make_float2(acc[i][j][2], acc[i][j][3]);
        }
    }
}

// ======= RMSNorm + RoPE, warp-per-head, no smem / no block syncs ============
// Block 256 = 8 warps; iteration 0: warps -> Q heads 0..7;
// iteration 1: warps 0..3 -> K heads, warps 4..7 -> V heads.
// Per-thread layout d = lane + 32*j: RoPE partner d+-128 is register j+-4.
__global__ __launch_bounds__(256)
void norm_rope3(const float* __restrict__ QKp, const float* __restrict__ Vp,
                const float* __restrict__ cosb, const float* __restrict__ sinb,
                const float* __restrict__ qw, const float* __restrict__ kw,
                __nv_bfloat16* __restrict__ Qrh, __nv_bfloat16* __restrict__ Qrl,
                __nv_bfloat16* __restrict__ Krh, __nv_bfloat16* __restrict__ Krl,
                __half* __restrict__ Vrf) {
    const int s = blockIdx.x;
    const int w = threadIdx.x >> 5;
    const int lane = threadIdx.x & 31;

#pragma unroll
    for (int it = 0; it < 2; it++) {
        const int slot = it * 8 + w;
        const float* src;
        const float* wp = nullptr;
        if (slot < HQ) {
            src = QKp + (size_t)s * NQK + slot * HD;
            wp = qw;
        } else if (slot < HQ + HKV) {
            src = QKp + (size_t)s * NQK + HQ * HD + (slot - HQ) * HD;
            wp = kw;
        } else {
            src = Vp + (size_t)s * (HKV * HD) + (slot - HQ - HKV) * HD;
        }

        float y[8];
        float v = 0.f;
#pragma unroll
        for (int j = 0; j < 8; j++) {
            y[j] = src[lane + 32 * j];
            v += y[j] * y[j];
        }
#pragma unroll
        for (int off = 16; off > 0; off >>= 1)
            v += __shfl_xor_sync(0xffffffffu, v, off);
        const float rms = rsqrtf(v * (1.0f / HD) + 1e-6f);
#pragma unroll
        for (int j = 0; j < 8; j++) y[j] *= rms;

        if (slot < HQ + HKV) {                 // Q/K: weight + RoPE
#pragma unroll
            for (int j = 0; j < 8; j++) y[j] *= wp[lane + 32 * j];
            float yr[8];
#pragma unroll
            for (int j = 0; j < 8; j++) yr[j] = (j < 4) ? -y[j + 4] : y[j - 4];
#pragma unroll
            for (int j = 0; j < 8; j++) {
                int d = lane + 32 * j;
                y[j] = y[j] * cosb[(size_t)s * HD + d] + yr[j] * sinb[(size_t)s * HD + d];
            }
            __nv_bfloat16* dh;
            __nv_bfloat16* dl;
            if (slot < HQ) {
                dh = Qrh + ((size_t)slot * S_LEN + s) * HD;
                dl = Qrl + ((size_t)slot * S_LEN + s) * HD;
            } else {
                dh = Krh + ((size_t)(slot - HQ) * S_LEN + s) * HD;
                dl = Krl + ((size_t)(slot - HQ) * S_LEN + s) * HD;
            }
#pragma unroll
            for (int j = 0; j < 8; j++) {
                __nv_bfloat16 hb = __float2bfloat16(y[j]);
                dh[lane + 32 * j] = hb;
                dl[lane + 32 * j] = __float2bfloat16(y[j] - __bfloat162float(hb));
            }
        } else {                               // V: fp16 single
            __half* dv = Vrf + ((size_t)(slot - HQ - HKV) * S_LEN + s) * HD;
#pragma unroll
            for (int j = 0; j < 8; j++)
                dv[lane + 32 * j] = __float2half_rn(y[j]);
        }
    }
}

// ================= HMMA flash attention (sliding window + softcap) =========
// QK: bf16 3-term. PV: fp16 2-term. Heavy-first block order.
#define APITCH 528
#define AQH_OFF 0
#define AQL_OFF 33792
#define AKH_OFF 67584
#define AKL_OFF 101376
#define AVF_OFF 135168
#define APH_OFF 168960
#define APL_OFF 178176
#define ASTAT_OFF 187392
#define SMEM_ATTN 189184

__global__ __launch_bounds__(256, 1)
void attn_mma(const __nv_bfloat16* __restrict__ Qh, const __nv_bfloat16* __restrict__ Ql,
              const __nv_bfloat16* __restrict__ Kh, const __nv_bfloat16* __restrict__ Kl,
              const __half* __restrict__ Vf,
              __half* __restrict__ AOh, __half* __restrict__ AOl) {
    extern __shared__ char smemc[];
    const uint32_t sb = smem_u32(smemc);
    const int tid = threadIdx.x;
    const int lane = tid & 31;
    const int w = tid >> 5;
    const int h = blockIdx.y;
    const int q0 = (gridDim.x - 1 - blockIdx.x) * 64;   // heavy-first

    const __nv_bfloat16* qhp = Qh + ((size_t)h * S_LEN + q0) * HD;
    const __nv_bfloat16* qlp = Ql + ((size_t)h * S_LEN + q0) * HD;
    const __nv_bfloat16* khp = Kh + (size_t)(h >> 1) * S_LEN * HD;
    const __nv_bfloat16* klp = Kl + (size_t)(h >> 1) * S_LEN * HD;
    const __half* vfp = Vf + (size_t)(h >> 1) * S_LEN * HD;

    float* marr  = (float*)(smemc + ASTAT_OFF);
    float* larr  = marr + 64;
    float* alpha = marr + 128;
    float* pm0   = marr + 192;
    float* pm1   = marr + 256;
    float* ps0   = marr + 320;
    float* ps1   = marr + 384;

    if (tid < 64) { marr[tid] = -1e30f; larr[tid] = 0.f; }

    auto cpQ = [&](uint32_t off, const __nv_bfloat16* src) {
#pragma unroll
        for (int i = 0; i < 8; i++) {
            int flat = tid + i * 256;
            int r = flat >> 5, c = flat & 31;
            CP_ASYNC16(sb + off + r * APITCH + c * 16, src + (size_t)r * HD + c * 8);
        }
    };
    auto cpT = [&](uint32_t off, const __nv_bfloat16* base, int kt) {
#pragma unroll
        for (int i = 0; i < 8; i++) {
            int flat = tid + i * 256;
            int r = flat >> 5, c = flat & 31;
            CP_ASYNC16(sb + off + r * APITCH + c * 16, base + (size_t)(kt + r) * HD + c * 8);
        }
    };
    auto cpV = [&](int kt) {
#pragma unroll
        for (int i = 0; i < 8; i++) {
            int flat = tid + i * 256;
            int r = flat >> 5, c = flat & 31;
            CP_ASYNC16(sb + AVF_OFF + r * APITCH + c * 16, vfp + (size_t)(kt + r) * HD + c * 8);
        }
    };

    int klo = q0 - (WIN - 1);
    if (klo < 0) klo = 0;
    const int kt0 = klo & ~63;

    cpQ(AQH_OFF, qhp); cpQ(AQL_OFF, qlp);
    cpT(AKH_OFF, khp, kt0); cpT(AKL_OFF, klp, kt0);
    CP_COMMIT();

    float oacc[16][4];
#pragma unroll
    for (int i = 0; i < 16; i++)
#pragma unroll
        for (int q = 0; q < 4; q++) oacc[i][q] = 0.f;

    const int aro = (lane & 7) + 8 * ((lane >> 3) & 1);
    const int aco = (lane >> 4) * 16;
    const int bro = (lane & 7) + 8 * ((lane >> 4) & 1);
    const int bco = ((lane >> 3) & 1) * 16;
    const int R  = 16 * (w >> 1);
    const int Ch = 32 * (w & 1);
    const int Rp = 16 * (w & 3);
    const int Dq = 128 * (w >> 2);
    const int rl = lane >> 2;

    __syncthreads();

    for (int kt = kt0; kt <= q0; kt += 64) {
        cpV(kt);
        CP_COMMIT();
        CP_WAIT1();
        __syncthreads();

        // ---------------- QK ----------------
        float sacc[4][4];
#pragma unroll
        for (int i = 0; i < 4; i++)
#pragma unroll
            for (int q = 0; q < 4; q++) sacc[i][q] = 0.f;

#pragma unroll
        for (int ks = 0; ks < 16; ks++) {
            uint32_t aH[4], aL[4];
            uint32_t ab = sb + AQH_OFF + (R + aro) * APITCH + ks * 32 + aco;
            ldsm4(aH, ab);
            ldsm4(aL, ab + (AQL_OFF - AQH_OFF));
            uint32_t bH0[4], bL0[4], bH1[4], bL1[4];
            uint32_t bb0 = sb + AKH_OFF + (Ch + bro) * APITCH + ks * 32 + bco;
            uint32_t bb1 = sb + AKH_OFF + (Ch + 16 + bro) * APITCH + ks * 32 + bco;
            ldsm4(bH0, bb0);
            ldsm4(bL0, bb0 + (AKL_OFF - AKH_OFF));
            ldsm4(bH1, bb1);
            ldsm4(bL1, bb1 + (AKL_OFF - AKH_OFF));
            mma16816(sacc[0], aH, bH0[0], bH0[1]);
            mma16816(sacc[1], aH, bH0[2], bH0[3]);
            mma16816(sacc[2], aH, bH1[0], bH1[1]);
            mma16816(sacc[3], aH, bH1[2], bH1[3]);
            mma16816(sacc[0], aH, bL0[0], bL0[1]);
            mma16816(sacc[1], aH, bL0[2], bL0[3]);
            mma16816(sacc[2], aH, bL1[0], bL1[1]);
            mma16816(sacc[3], aH, bL1[2], bL1[3]);
            mma16816(sacc[0], aL, bH0[0], bH0[1]);
            mma16816(sacc[1], aL, bH0[2], bH0[3]);
            mma16816(sacc[2], aL, bH1[0], bH1[1]);
            mma16816(sacc[3], aL, bH1[2], bH1[3]);
        }

        const int rlo = R + rl, rhi = R + rl + 8;
        float mx0 = -1e30f, mx1 = -1e30f;
#pragma unroll
        for (int n8 = 0; n8 < 4; n8++) {
#pragma unroll
            for (int e = 0; e < 4; e++) {
                int row = (e < 2) ? rlo : rhi;
                int kg = kt + Ch + n8 * 8 + (lane & 3) * 2 + (e & 1);
                int qg = q0 + row;
                float s = softcap50(sacc[n8][e]);
                bool ok = (kg <= qg) && (qg - kg < WIN);
                s = ok ? s : -1e30f;
                sacc[n8][e] = s;
                if (e < 2) mx0 = fmaxf(mx0, s); else mx1 = fmaxf(mx1, s);
            }
        }
        mx0 = fmaxf(mx0, __shfl_xor_sync(0xffffffffu, mx0, 1));
        mx0 = fmaxf(mx0, __shfl_xor_sync(0xffffffffu, mx0, 2));
        mx1 = fmaxf(mx1, __shfl_xor_sync(0xffffffffu, mx1, 1));
        mx1 = fmaxf(mx1, __shfl_xor_sync(0xffffffffu, mx1, 2));
        if ((lane & 3) == 0) {
            float* pmh = (w & 1) ? pm1 : pm0;
            pmh[rlo] = mx0; pmh[rhi] = mx1;
        }
        __syncthreads();

        if (kt + 64 <= q0) { cpT(AKH_OFF, khp, kt + 64); cpT(AKL_OFF, klp, kt + 64); }
        CP_COMMIT();

        if (tid < 64) {
            float mo = marr[tid];
            float mn = fmaxf(mo, fmaxf(pm0[tid], pm1[tid]));
            alpha[tid] = (mn > -1e29f) ? __expf(mo - mn) : 1.f;
            marr[tid] = mn;
        }
        __syncthreads();

        {
            float mn0 = marr[rlo], mn1 = marr[rhi];
            float sum0 = 0.f, sum1 = 0.f;
#pragma unroll
            for (int n8 = 0; n8 < 4; n8++) {
                float p0 = (sacc[n8][0] > -1e29f) ? __expf(sacc[n8][0] - mn0) : 0.f;
                float p1 = (sacc[n8][1] > -1e29f) ? __expf(sacc[n8][1] - mn0) : 0.f;
                float p2 = (sacc[n8][2] > -1e29f) ? __expf(sacc[n8][2] - mn1) : 0.f;
                float p3 = (sacc[n8][3] > -1e29f) ? __expf(sacc[n8][3] - mn1) : 0.f;
                sum0 += p0 + p1; sum1 += p2 + p3;
                int cb = (Ch + n8 * 8 + (lane & 3) * 2) * 2;
                uint32_t hlo = pack2h(p0, p1);
                uint32_t hhi = pack2h(p2, p3);
                __half2 hv0 = *(__half2*)&hlo;
                __half2 hv1 = *(__half2*)&hhi;
                *(uint32_t*)(smemc + APH_OFF + rlo * 144 + cb) = hlo;
                *(uint32_t*)(smemc + APH_OFF + rhi * 144 + cb) = hhi;
                *(uint32_t*)(smemc + APL_OFF + rlo * 144 + cb) =
                    pack2h(p0 - __half2float(hv0.x), p1 - __half2float(hv0.y));
                *(uint32_t*)(smemc + APL_OFF + rhi * 144 + cb) =
                    pack2h(p2 - __half2float(hv1.x), p3 - __half2float(hv1.y));
            }
            sum0 += __shfl_xor_sync(0xffffffffu, sum0, 1);
            sum0 += __shfl_xor_sync(0xffffffffu, sum0, 2);
            sum1 += __shfl_xor_sync(0xffffffffu, sum1, 1);
            sum1 += __shfl_xor_sync(0xffffffffu, sum1, 2);
            if ((lane & 3) == 0) {
                float* psh = (w & 1) ? ps1 : ps0;
                psh[rlo] = sum0; psh[rhi] = sum1;
            }
        }
        __syncthreads();
        if (tid < 64) larr[tid] = alpha[tid] * larr[tid] + ps0[tid] + ps1[tid];
        CP_WAIT1();
        __syncthreads();

        // ---------------- PV (fp16 2-term) ----------------
        {
            float a0 = alpha[Rp + rl], a1 = alpha[Rp + 8 + rl];
#pragma unroll
            for (int n8 = 0; n8 < 16; n8++) {
                oacc[n8][0] *= a0; oacc[n8][1] *= a0;
                oacc[n8][2] *= a1; oacc[n8][3] *= a1;
            }
            const int vco = ((lane >> 4) & 1) * 8;
            const int vrw = (lane & 7) + 8 * ((lane >> 3) & 1);
#pragma unroll
            for (int ks = 0; ks < 4; ks++) {
                uint32_t pH[4], pL[4];
                uint32_t pb = sb + APH_OFF + (Rp + aro) * 144 + ks * 32 + aco;
                ldsm4(pH, pb);
                ldsm4(pL, pb + (APL_OFF - APH_OFF));
#pragma unroll
                for (int dt = 0; dt < 8; dt += 2) {
                    uint32_t vH0[4], vH1[4];
                    uint32_t vb0 = sb + AVF_OFF + (ks * 16 + vrw) * APITCH +
                                   (Dq + dt * 16 + vco) * 2;
                    uint32_t vb1 = vb0 + 32;
                    ldsm4t(vH0, vb0);
                    ldsm4t(vH1, vb1);
                    mma16816h(oacc[2 * dt],     pH, vH0[0], vH0[1]);
                    mma16816h(oacc[2 * dt + 1], pH, vH0[2], vH0[3]);
                    mma16816h(oacc[2 * dt + 2], pH, vH1[0], vH1[1]);
                    mma16816h(oacc[2 * dt + 3], pH, vH1[2], vH1[3]);
                    mma16816h(oacc[2 * dt],     pL, vH0[0], vH0[1]);
                    mma16816h(oacc[2 * dt + 1], pL, vH0[2], vH0[3]);
                    mma16816h(oacc[2 * dt + 2], pL, vH1[0], vH1[1]);
                    mma16816h(oacc[2 * dt + 3], pL, vH1[2], vH1[3]);
                }
            }
        }
        __syncthreads();
    }

    // output: fp16 hi/lo, [S][HQ*HD]
    {
        float inv0 = 1.0f / larr[Rp + rl];
        float inv1 = 1.0f / larr[Rp + 8 + rl];
        const int r0 = q0 + Rp + rl;
#pragma unroll
        for (int n8 = 0; n8 < 16; n8++) {
            int col = h * HD + Dq + n8 * 8 + (lane & 3) * 2;
            float o0 = oacc[n8][0] * inv0, o1 = oacc[n8][1] * inv0;
            float o2 = oacc[n8][2] * inv1, o3 = oacc[n8][3] * inv1;
            uint32_t h0 = pack2h(o0, o1);
            __half2 hv0 = *(__half2*)&h0;
            uint32_t l0 = pack2h(o0 - __half2float(hv0.x), o1 - __half2float(hv0.y));
            uint32_t h1 = pack2h(o2, o3);
            __half2 hv1 = *(__half2*)&h1;
            uint32_t l1 = pack2h(o2 - __half2float(hv1.x), o3 - __half2float(hv1.y));
            *(uint32_t*)(AOh + (size_t)r0 * (HQ * HD) + col) = h0;
            *(uint32_t*)(AOl + (size_t)r0 * (HQ * HD) + col) = l0;
            *(uint32_t*)(AOh + (size_t)(r0 + 8) * (HQ * HD) + col) = h1;
            *(uint32_t*)(AOl + (size_t)(r0 + 8) * (HQ * HD) + col) = l1;
        }
    }
}

// ================= launch =================
extern "C" void kernel_launch(void* const* d_in, const int* in_sizes, int n_in,
                              void* d_out, int out_size) {
    const float* hidden = (const float*)d_in[0];
    const float* cosb   = (const float*)d_in[1];
    const float* sinb   = (const float*)d_in[2];
    // d_in[3] = attention_mask (sliding window, implemented analytically)
    const float* Wq = (const float*)d_in[4];
    const float* Wk = (const float*)d_in[5];
    const float* Wv = (const float*)d_in[6];
    const float* Wo = (const float*)d_in[7];
    const float* qw = (const float*)d_in[8];
    const float* kw = (const float*)d_in[9];
    float* out = (float*)d_out;

    float *QKp, *Vp;
    cudaGetSymbolAddress((void**)&QKp, g_QKp);
    cudaGetSymbolAddress((void**)&Vp, g_Vp);

    __nv_bfloat16 *hidh, *hidl, *wqkh, *wqkl;
    __half *hidfh, *hidfl, *wvf, *wof, *aofh, *aofl, *vrf;
    __nv_bfloat16 *qrh, *qrl, *krh, *krl;
    cudaGetSymbolAddress((void**)&hidh, g_hid_h);
    cudaGetSymbolAddress((void**)&hidl, g_hid_l);
    cudaGetSymbolAddress((void**)&hidfh, g_hid_fh);
    cudaGetSymbolAddress((void**)&hidfl, g_hid_fl);
    cudaGetSymbolAddress((void**)&wqkh, g_wqk_h);
    cudaGetSymbolAddress((void**)&wqkl, g_wqk_l);
    cudaGetSymbolAddress((void**)&wvf, g_wv_f);
    cudaGetSymbolAddress((void**)&wof, g_wo_f);
    cudaGetSymbolAddress((void**)&aofh, g_ao_fh);
    cudaGetSymbolAddress((void**)&aofl, g_ao_fl);
    cudaGetSymbolAddress((void**)&qrh, g_qr_h);
    cudaGetSymbolAddress((void**)&qrl, g_qr_l);
    cudaGetSymbolAddress((void**)&krh, g_kr_h);
    cudaGetSymbolAddress((void**)&krl, g_kr_l);
    cudaGetSymbolAddress((void**)&vrf, g_vr_f);

    cudaFuncSetAttribute((const void*)gemm_bf16x3,
                         cudaFuncAttributeMaxDynamicSharedMemorySize, SMEM_GEMM);
    cudaFuncSetAttribute((const void*)gemm_fp16x2,
                         cudaFuncAttributeMaxDynamicSharedMemorySize, SMEM_GEMM_F);
    cudaFuncSetAttribute((const void*)attn_mma,
                         cudaFuncAttributeMaxDynamicSharedMemorySize, SMEM_ATTN);

    // fused conversions (one launch, 4x ILP)
    cvt_all<<<(CVT_THREADS + 255) / 256, 256>>>(
        (const float4*)hidden, (const float4*)Wq, (const float4*)Wk,
        (const float4*)Wv, (const float4*)Wo,
        hidh, hidl, hidfh, hidfl, wqkh, wqkl, wvf, wof);

    // combined Q|K projection: bf16 3-term
    gemm_bf16x3<<<dim3(NQK / 128, 64), 128, SMEM_GEMM>>>(hidh, hidl, wqkh, wqkl,
                                                         QKp, NQK, H_DIM);
    // V projection: fp16 2-term
    gemm_fp16x2<<<dim3(8, 64), 128, SMEM_GEMM_F>>>(hidfh, hidfl, wvf, Vp, HKV * HD, H_DIM);

    // RMSNorm + RoPE (warp-per-head, sync-free)
    norm_rope3<<<S_LEN, 256>>>(QKp, Vp, cosb, sinb, qw, kw,
                               qrh, qrl, krh, krl, vrf);

    // tensor-core flash attention -> fp16 hi/lo AO (heavy-first order)
    attn_mma<<<dim3(S_LEN / 64, HQ), 256, SMEM_ATTN>>>(qrh, qrl, krh, krl, vrf, aofh, aofl);

    // output projection: fp16 2-term
    gemm_fp16x2<<<dim3(16, 64), 128, SMEM_GEMM_F>>>(aofh, aofl, wof, out, H_DIM, H_DIM);
}